// round 1
// baseline (speedup 1.0000x reference)
#include <cuda_runtime.h>

// Problem constants
#define Bc   8
#define Nn   2048
#define Kn   32
#define Fin  256
#define Cch  512
#define Mrows (Bc * Nn)   // 16384

// Scratch (no allocations allowed -> __device__ globals)
__device__ float g_xneib[Bc * Nn * Fin];      // 16.8 MB
__device__ float g_stats[2 * Cch];            // channel sum, sumsq
__device__ float g_scale[Cch];
__device__ float g_shift[Cch];

// ---------------------------------------------------------------------------
// Zero the BN stats accumulators (must be re-zeroed every launch)
// ---------------------------------------------------------------------------
__global__ void zero_stats_kernel() {
    int i = blockIdx.x * blockDim.x + threadIdx.x;
    if (i < 2 * Cch) g_stats[i] = 0.0f;
}

// ---------------------------------------------------------------------------
// Gather-mean: x_neib[b,n,:] = mean_k x[b, idx[n,k], :]
// One block per (n, b); 256 threads = one feature each.
// 4 independent partial accumulators for MLP.
// ---------------------------------------------------------------------------
__global__ __launch_bounds__(Fin) void gather_mean_kernel(
    const float* __restrict__ x, const int* __restrict__ idx)
{
    __shared__ int sidx[Kn];
    const int n = blockIdx.x;
    const int b = blockIdx.y;
    const int t = threadIdx.x;

    if (t < Kn) sidx[t] = idx[n * Kn + t];
    __syncthreads();

    const float* xb = x + (size_t)b * Nn * Fin;
    float a0 = 0.f, a1 = 0.f, a2 = 0.f, a3 = 0.f;
#pragma unroll
    for (int k = 0; k < Kn; k += 4) {
        a0 += xb[sidx[k + 0] * Fin + t];
        a1 += xb[sidx[k + 1] * Fin + t];
        a2 += xb[sidx[k + 2] * Fin + t];
        a3 += xb[sidx[k + 3] * Fin + t];
    }
    g_xneib[((size_t)b * Nn + n) * Fin + t] = (a0 + a1 + a2 + a3) * (1.0f / Kn);
}

// ---------------------------------------------------------------------------
// fp32 GEMM with packed f32x2 FMA.
// C[m, coloff + o] = sum_f A[m,f] * W[o,f] + bias[o]
// A: [Mrows, 256] row-major.  W: [256, 256] row-major (torch [out,in]).
// BM=BN=64, BK=32, 256 threads, each thread 4x4 outputs.
// Accumulators are f32x2 pairs over (even-k, odd-k) partial sums; both smem
// operand reads are contiguous 8B loads -> no pack instructions, fma-bound.
// Column mapping per thread: tx + 16*j (stride-16 interleave) -> conflict-free
// 64-bit smem reads with row stride 34 floats (136B, 8B-aligned).
// ---------------------------------------------------------------------------
#define SLD 34

template<int USE_XNEIB>
__global__ __launch_bounds__(256) void gemm_bias_kernel(
    const float* __restrict__ Ain, const float* __restrict__ W,
    const float* __restrict__ bias, float* __restrict__ C, int coloff)
{
    __shared__ __align__(16) float As[64 * SLD];
    __shared__ __align__(16) float Ws[64 * SLD];

    const float* A = USE_XNEIB ? g_xneib : Ain;

    const int tid = threadIdx.x;
    const int tx = tid & 15;        // column group
    const int ty = tid >> 4;        // row group
    const int m0 = blockIdx.x * 64;
    const int n0 = blockIdx.y * 64;

    const int lr = tid >> 3;        // 0..31  (load row)
    const int lc = (tid & 7) << 2;  // 0,4,...,28 (load col, float4)

    unsigned long long acc[4][4];
#pragma unroll
    for (int i = 0; i < 4; i++)
#pragma unroll
        for (int j = 0; j < 4; j++) acc[i][j] = 0ull;

    for (int k0 = 0; k0 < Fin; k0 += 32) {
#pragma unroll
        for (int it = 0; it < 2; it++) {
            int r = lr + it * 32;
            float4 av = *(const float4*)&A[(size_t)(m0 + r) * Fin + k0 + lc];
            float* ad = &As[r * SLD + lc];
            *(float2*)(ad)     = make_float2(av.x, av.y);
            *(float2*)(ad + 2) = make_float2(av.z, av.w);
            float4 wv = *(const float4*)&W[(size_t)(n0 + r) * Fin + k0 + lc];
            float* wd = &Ws[r * SLD + lc];
            *(float2*)(wd)     = make_float2(wv.x, wv.y);
            *(float2*)(wd + 2) = make_float2(wv.z, wv.w);
        }
        __syncthreads();

#pragma unroll
        for (int kp = 0; kp < 16; kp++) {
            unsigned long long a2[4], b2[4];
#pragma unroll
            for (int i = 0; i < 4; i++)
                a2[i] = *(const unsigned long long*)&As[(ty * 4 + i) * SLD + kp * 2];
#pragma unroll
            for (int j = 0; j < 4; j++)
                b2[j] = *(const unsigned long long*)&Ws[(tx + 16 * j) * SLD + kp * 2];
#pragma unroll
            for (int i = 0; i < 4; i++)
#pragma unroll
                for (int j = 0; j < 4; j++)
                    asm("fma.rn.f32x2 %0, %1, %2, %0;"
                        : "+l"(acc[i][j]) : "l"(a2[i]), "l"(b2[j]));
        }
        __syncthreads();
    }

#pragma unroll
    for (int i = 0; i < 4; i++) {
        int m = m0 + ty * 4 + i;
#pragma unroll
        for (int j = 0; j < 4; j++) {
            int c = n0 + tx + 16 * j;
            unsigned long long v = acc[i][j];
            float lo = __uint_as_float((unsigned)(v & 0xffffffffull));
            float hi = __uint_as_float((unsigned)(v >> 32));
            C[(size_t)m * Cch + coloff + c] = lo + hi + bias[c];
        }
    }
}

// ---------------------------------------------------------------------------
// Per-row L2 normalize + ReLU, accumulate per-channel BN stats.
// 512 threads = one channel each; R rows per block.
// ---------------------------------------------------------------------------
#define ROWS_PER_BLK 16

__global__ __launch_bounds__(Cch) void norm_relu_stats_kernel(float* __restrict__ h)
{
    __shared__ float sbuf[32];  // 16 warps x 2 parity halves
    const int t = threadIdx.x;
    const int w = t >> 5, lane = t & 31;
    const int row0 = blockIdx.x * ROWS_PER_BLK;

    float csum = 0.f, csq = 0.f;
    for (int r = 0; r < ROWS_PER_BLK; r++) {
        size_t off = (size_t)(row0 + r) * Cch + t;
        float v = h[off];
        float s = v * v;
#pragma unroll
        for (int o = 16; o; o >>= 1) s += __shfl_xor_sync(0xffffffffu, s, o);
        if (lane == 0) sbuf[(r & 1) * 16 + w] = s;
        __syncthreads();
        float tot = 0.f;
#pragma unroll
        for (int i = 0; i < 16; i++) tot += sbuf[(r & 1) * 16 + i];
        float inv = 1.0f / fmaxf(sqrtf(tot), 1e-12f);
        v = fmaxf(v * inv, 0.0f);
        h[off] = v;
        csum += v;
        csq += v * v;
    }
    atomicAdd(&g_stats[t], csum);
    atomicAdd(&g_stats[Cch + t], csq);
}

// ---------------------------------------------------------------------------
// BN finalize: per-channel scale/shift from accumulated stats.
// ---------------------------------------------------------------------------
__global__ void bn_finalize_kernel(const float* __restrict__ gamma,
                                   const float* __restrict__ beta)
{
    int c = threadIdx.x;
    const float invM = 1.0f / (float)Mrows;
    float mu  = g_stats[c] * invM;
    float var = g_stats[Cch + c] * invM - mu * mu;
    float sc  = gamma[c] * rsqrtf(var + 1e-5f);
    g_scale[c] = sc;
    g_shift[c] = beta[c] - mu * sc;
}

// ---------------------------------------------------------------------------
// BN apply: h = h * scale[c] + shift[c]   (vectorized float4)
// ---------------------------------------------------------------------------
__global__ __launch_bounds__(256) void bn_apply_kernel(float* __restrict__ h)
{
    int i = blockIdx.x * blockDim.x + threadIdx.x;   // float4 index
    float4 v = ((float4*)h)[i];
    int c = (i << 2) & (Cch - 1);
    v.x = v.x * g_scale[c + 0] + g_shift[c + 0];
    v.y = v.y * g_scale[c + 1] + g_shift[c + 1];
    v.z = v.z * g_scale[c + 2] + g_shift[c + 2];
    v.w = v.w * g_scale[c + 3] + g_shift[c + 3];
    ((float4*)h)[i] = v;
}

// ---------------------------------------------------------------------------
// Launch
// Inputs (metadata order): x, idx_neib, Wx_w, Wx_b, Wn_w, Wn_b, gamma, beta
// Output: [B, N, 512] float32
// ---------------------------------------------------------------------------
extern "C" void kernel_launch(void* const* d_in, const int* in_sizes, int n_in,
                              void* d_out, int out_size)
{
    const float* x     = (const float*)d_in[0];
    const int*   idx   = (const int*)  d_in[1];
    const float* Wx_w  = (const float*)d_in[2];
    const float* Wx_b  = (const float*)d_in[3];
    const float* Wn_w  = (const float*)d_in[4];
    const float* Wn_b  = (const float*)d_in[5];
    const float* gamma = (const float*)d_in[6];
    const float* beta  = (const float*)d_in[7];
    float* out = (float*)d_out;

    zero_stats_kernel<<<2, 512>>>();
    gather_mean_kernel<<<dim3(Nn, Bc), Fin>>>(x, idx);

    dim3 ggrid(Mrows / 64, Fin / 64);  // 256 x 4
    gemm_bias_kernel<0><<<ggrid, 256>>>(x,       Wx_w, Wx_b, out, 0);
    gemm_bias_kernel<1><<<ggrid, 256>>>(nullptr, Wn_w, Wn_b, out, 256);

    norm_relu_stats_kernel<<<Mrows / ROWS_PER_BLK, Cch>>>(out);
    bn_finalize_kernel<<<1, Cch>>>(gamma, beta);
    bn_apply_kernel<<<(Mrows * Cch / 4) / 256, 256>>>(out);
}

// round 2
// speedup vs baseline: 1.0487x; 1.0487x over previous
#include <cuda_runtime.h>

// Problem constants
#define Bc   8
#define Nn   2048
#define Kn   32
#define Fin  256
#define Cch  512
#define Mrows (Bc * Nn)   // 16384

// Scratch (no allocations allowed -> __device__ globals)
__device__ float g_xneib[Bc * Nn * Fin];      // 16.8 MB
__device__ float g_stats[2 * Cch];            // channel sum, sumsq
__device__ float g_scale[Cch];
__device__ float g_shift[Cch];

// ---------------------------------------------------------------------------
// Zero the BN stats accumulators (must be re-zeroed every launch)
// ---------------------------------------------------------------------------
__global__ void zero_stats_kernel() {
    int i = blockIdx.x * blockDim.x + threadIdx.x;
    if (i < 2 * Cch) g_stats[i] = 0.0f;
}

// ---------------------------------------------------------------------------
// Gather-mean: x_neib[b,n,:] = mean_k x[b, idx[n,k], :]
// One block per (n, b); 256 threads = one feature each. L2-bound (~48us floor).
// ---------------------------------------------------------------------------
__global__ __launch_bounds__(Fin) void gather_mean_kernel(
    const float* __restrict__ x, const int* __restrict__ idx)
{
    __shared__ int sidx[Kn];
    const int n = blockIdx.x;
    const int b = blockIdx.y;
    const int t = threadIdx.x;

    if (t < Kn) sidx[t] = idx[n * Kn + t];
    __syncthreads();

    const float* xb = x + (size_t)b * Nn * Fin;
    float a0 = 0.f, a1 = 0.f, a2 = 0.f, a3 = 0.f;
#pragma unroll
    for (int k = 0; k < Kn; k += 4) {
        a0 += xb[sidx[k + 0] * Fin + t];
        a1 += xb[sidx[k + 1] * Fin + t];
        a2 += xb[sidx[k + 2] * Fin + t];
        a3 += xb[sidx[k + 3] * Fin + t];
    }
    g_xneib[((size_t)b * Nn + n) * Fin + t] = (a0 + a1 + a2 + a3) * (1.0f / Kn);
}

// ---------------------------------------------------------------------------
// fp32 GEMM, packed f32x2 FMA, rebalanced for the smem crossbar.
// C[m, coloff + o] = sum_f A[m,f] * W[o,f] + bias[o]
// BM=128, BN=64, BK=32, 256 threads, per-thread 8x4 outputs.
//   rows  = ty + 16*i  (i<8)  -> A-operand LDS broadcast within warp (2 distinct
//                               addrs / 32 lanes): ~16B crossbar per LDS.64
//   cols  = tx + 16*j  (j<4)  -> B-operand LDS conflict-free (banks 2*tx)
// Per kp: 12 LDS.64 (640B crossbar) vs 32 FFMA2 -> fma-bound.
// ---------------------------------------------------------------------------
#define SLD 34

template<int USE_XNEIB>
__global__ __launch_bounds__(256, 2) void gemm_bias_kernel(
    const float* __restrict__ Ain, const float* __restrict__ W,
    const float* __restrict__ bias, float* __restrict__ C, int coloff)
{
    __shared__ __align__(16) float As[128 * SLD];
    __shared__ __align__(16) float Ws[64 * SLD];

    const float* A = USE_XNEIB ? g_xneib : Ain;

    const int tid = threadIdx.x;
    const int tx = tid & 15;        // column group (0..15)
    const int ty = tid >> 4;        // row group (0..15)
    const int m0 = blockIdx.x * 128;
    const int n0 = blockIdx.y * 64;

    const int lr = tid >> 3;        // 0..31  (load row)
    const int lc = (tid & 7) << 2;  // 0,4,...,28 (load col, float4)

    unsigned long long acc[8][4];
#pragma unroll
    for (int i = 0; i < 8; i++)
#pragma unroll
        for (int j = 0; j < 4; j++) acc[i][j] = 0ull;

    for (int k0 = 0; k0 < Fin; k0 += 32) {
#pragma unroll
        for (int it = 0; it < 4; it++) {           // A tile: 128 x 32
            int r = lr + it * 32;
            float4 av = *(const float4*)&A[(size_t)(m0 + r) * Fin + k0 + lc];
            float* ad = &As[r * SLD + lc];
            *(float2*)(ad)     = make_float2(av.x, av.y);
            *(float2*)(ad + 2) = make_float2(av.z, av.w);
        }
#pragma unroll
        for (int it = 0; it < 2; it++) {           // W tile: 64 x 32
            int r = lr + it * 32;
            float4 wv = *(const float4*)&W[(size_t)(n0 + r) * Fin + k0 + lc];
            float* wd = &Ws[r * SLD + lc];
            *(float2*)(wd)     = make_float2(wv.x, wv.y);
            *(float2*)(wd + 2) = make_float2(wv.z, wv.w);
        }
        __syncthreads();

#pragma unroll
        for (int kp = 0; kp < 16; kp++) {
            unsigned long long a2[8], b2[4];
#pragma unroll
            for (int j = 0; j < 4; j++)
                b2[j] = *(const unsigned long long*)&Ws[(tx + 16 * j) * SLD + kp * 2];
#pragma unroll
            for (int i = 0; i < 8; i++)
                a2[i] = *(const unsigned long long*)&As[(ty + 16 * i) * SLD + kp * 2];
#pragma unroll
            for (int i = 0; i < 8; i++)
#pragma unroll
                for (int j = 0; j < 4; j++)
                    asm("fma.rn.f32x2 %0, %1, %2, %0;"
                        : "+l"(acc[i][j]) : "l"(a2[i]), "l"(b2[j]));
        }
        __syncthreads();
    }

#pragma unroll
    for (int i = 0; i < 8; i++) {
        int m = m0 + ty + 16 * i;
#pragma unroll
        for (int j = 0; j < 4; j++) {
            int c = n0 + tx + 16 * j;
            unsigned long long v = acc[i][j];
            float lo = __uint_as_float((unsigned)(v & 0xffffffffull));
            float hi = __uint_as_float((unsigned)(v >> 32));
            C[(size_t)m * Cch + coloff + c] = lo + hi + bias[c];
        }
    }
}

// ---------------------------------------------------------------------------
// Per-row L2 normalize + ReLU, accumulate per-channel BN stats.
// ---------------------------------------------------------------------------
#define ROWS_PER_BLK 16

__global__ __launch_bounds__(Cch) void norm_relu_stats_kernel(float* __restrict__ h)
{
    __shared__ float sbuf[32];  // 16 warps x 2 parity halves
    const int t = threadIdx.x;
    const int w = t >> 5, lane = t & 31;
    const int row0 = blockIdx.x * ROWS_PER_BLK;

    float csum = 0.f, csq = 0.f;
    for (int r = 0; r < ROWS_PER_BLK; r++) {
        size_t off = (size_t)(row0 + r) * Cch + t;
        float v = h[off];
        float s = v * v;
#pragma unroll
        for (int o = 16; o; o >>= 1) s += __shfl_xor_sync(0xffffffffu, s, o);
        if (lane == 0) sbuf[(r & 1) * 16 + w] = s;
        __syncthreads();
        float tot = 0.f;
#pragma unroll
        for (int i = 0; i < 16; i++) tot += sbuf[(r & 1) * 16 + i];
        float inv = 1.0f / fmaxf(sqrtf(tot), 1e-12f);
        v = fmaxf(v * inv, 0.0f);
        h[off] = v;
        csum += v;
        csq += v * v;
    }
    atomicAdd(&g_stats[t], csum);
    atomicAdd(&g_stats[Cch + t], csq);
}

// ---------------------------------------------------------------------------
// BN finalize: per-channel scale/shift from accumulated stats.
// ---------------------------------------------------------------------------
__global__ void bn_finalize_kernel(const float* __restrict__ gamma,
                                   const float* __restrict__ beta)
{
    int c = threadIdx.x;
    const float invM = 1.0f / (float)Mrows;
    float mu  = g_stats[c] * invM;
    float var = g_stats[Cch + c] * invM - mu * mu;
    float sc  = gamma[c] * rsqrtf(var + 1e-5f);
    g_scale[c] = sc;
    g_shift[c] = beta[c] - mu * sc;
}

// ---------------------------------------------------------------------------
// BN apply: h = h * scale[c] + shift[c]   (vectorized float4)
// ---------------------------------------------------------------------------
__global__ __launch_bounds__(256) void bn_apply_kernel(float* __restrict__ h)
{
    int i = blockIdx.x * blockDim.x + threadIdx.x;   // float4 index
    float4 v = ((float4*)h)[i];
    int c = (i << 2) & (Cch - 1);
    v.x = v.x * g_scale[c + 0] + g_shift[c + 0];
    v.y = v.y * g_scale[c + 1] + g_shift[c + 1];
    v.z = v.z * g_scale[c + 2] + g_shift[c + 2];
    v.w = v.w * g_scale[c + 3] + g_shift[c + 3];
    ((float4*)h)[i] = v;
}

// ---------------------------------------------------------------------------
// Launch. Fork a second stream so the fma-bound self-GEMM overlaps the
// L2-bound gather (independent work). Falls back to serial if the fork
// stream can't be created.
// Inputs: x, idx_neib, Wx_w, Wx_b, Wn_w, Wn_b, gamma, beta
// ---------------------------------------------------------------------------
extern "C" void kernel_launch(void* const* d_in, const int* in_sizes, int n_in,
                              void* d_out, int out_size)
{
    const float* x     = (const float*)d_in[0];
    const int*   idx   = (const int*)  d_in[1];
    const float* Wx_w  = (const float*)d_in[2];
    const float* Wx_b  = (const float*)d_in[3];
    const float* Wn_w  = (const float*)d_in[4];
    const float* Wn_b  = (const float*)d_in[5];
    const float* gamma = (const float*)d_in[6];
    const float* beta  = (const float*)d_in[7];
    float* out = (float*)d_out;

    static cudaStream_t s2 = nullptr;
    static cudaEvent_t ev_fork = nullptr, ev_join = nullptr;
    static int stream_ok = -1;
    if (stream_ok < 0) {
        stream_ok = (cudaStreamCreateWithFlags(&s2, cudaStreamNonBlocking) == cudaSuccess &&
                     cudaEventCreateWithFlags(&ev_fork, cudaEventDisableTiming) == cudaSuccess &&
                     cudaEventCreateWithFlags(&ev_join, cudaEventDisableTiming) == cudaSuccess)
                        ? 1 : 0;
    }

    dim3 ggrid(Mrows / 128, 64 / 64 * (Fin / 64));  // 128 x 4

    if (stream_ok) {
        // Fork: branch B = gather -> neighbor GEMM (on s2)
        cudaEventRecord(ev_fork, 0);
        cudaStreamWaitEvent(s2, ev_fork, 0);
        gather_mean_kernel<<<dim3(Nn, Bc), Fin, 0, s2>>>(x, idx);
        gemm_bias_kernel<1><<<ggrid, 256, 0, s2>>>(nullptr, Wn_w, Wn_b, out, 256);
        cudaEventRecord(ev_join, s2);

        // Branch A (main stream): stats zero + self GEMM
        zero_stats_kernel<<<2, 512>>>();
        gemm_bias_kernel<0><<<ggrid, 256>>>(x, Wx_w, Wx_b, out, 0);

        cudaStreamWaitEvent(0, ev_join, 0);
    } else {
        zero_stats_kernel<<<2, 512>>>();
        gather_mean_kernel<<<dim3(Nn, Bc), Fin>>>(x, idx);
        gemm_bias_kernel<0><<<ggrid, 256>>>(x, Wx_w, Wx_b, out, 0);
        gemm_bias_kernel<1><<<ggrid, 256>>>(nullptr, Wn_w, Wn_b, out, 256);
    }

    norm_relu_stats_kernel<<<Mrows / ROWS_PER_BLK, Cch>>>(out);
    bn_finalize_kernel<<<1, Cch>>>(gamma, beta);
    bn_apply_kernel<<<(Mrows * Cch / 4) / 256, 256>>>(out);
}

// round 4
// speedup vs baseline: 1.4932x; 1.4238x over previous
#include <cuda_runtime.h>
#include <cuda_bf16.h>
#include <cstdint>

// Problem constants
#define Bc   8
#define Nn   2048
#define Kn   32
#define Fin  256
#define Cch  512
#define Mrows 16384
#define Ktot 768            // 3-term bf16 split: [hi | lo | hi] x [hi | hi | lo]

// ---------------------------------------------------------------------------
// Device-global scratch (no allocations allowed)
// ---------------------------------------------------------------------------
__device__ __align__(16) __nv_bfloat16 g_Aself[Mrows * Ktot];   // 25.2 MB
__device__ __align__(16) __nv_bfloat16 g_Aneib[Mrows * Ktot];   // 25.2 MB
__device__ __align__(16) __nv_bfloat16 g_Wbf[2][256 * Ktot];    // 2 x 393 KB
__device__ float g_stats[2 * Cch];

// ---------------------------------------------------------------------------
// Zero BN stats
// ---------------------------------------------------------------------------
__global__ void zero_stats_kernel() {
    int i = blockIdx.x * blockDim.x + threadIdx.x;
    if (i < 2 * Cch) g_stats[i] = 0.0f;
}

// ---------------------------------------------------------------------------
// Gather-mean fused with bf16 hi/lo split output (row-major [m][768]).
// One block per (n, b); 256 threads = one feature each.
// ---------------------------------------------------------------------------
__global__ __launch_bounds__(Fin) void gather_mean_bf16_kernel(
    const float* __restrict__ x, const int* __restrict__ idx)
{
    __shared__ int sidx[Kn];
    const int n = blockIdx.x, b = blockIdx.y, t = threadIdx.x;
    if (t < Kn) sidx[t] = idx[n * Kn + t];
    __syncthreads();
    const float* xb = x + (size_t)b * Nn * Fin;
    float a0 = 0.f, a1 = 0.f, a2 = 0.f, a3 = 0.f, a4 = 0.f, a5 = 0.f, a6 = 0.f, a7 = 0.f;
#pragma unroll
    for (int k = 0; k < Kn; k += 8) {
        a0 += xb[sidx[k + 0] * Fin + t];
        a1 += xb[sidx[k + 1] * Fin + t];
        a2 += xb[sidx[k + 2] * Fin + t];
        a3 += xb[sidx[k + 3] * Fin + t];
        a4 += xb[sidx[k + 4] * Fin + t];
        a5 += xb[sidx[k + 5] * Fin + t];
        a6 += xb[sidx[k + 6] * Fin + t];
        a7 += xb[sidx[k + 7] * Fin + t];
    }
    float m = (((a0 + a1) + (a2 + a3)) + ((a4 + a5) + (a6 + a7))) * (1.0f / Kn);
    __nv_bfloat16 hi = __float2bfloat16_rn(m);
    __nv_bfloat16 lo = __float2bfloat16_rn(m - __bfloat162float(hi));
    __nv_bfloat16* o = g_Aneib + ((size_t)b * Nn + n) * Ktot;
    o[t] = hi; o[256 + t] = lo; o[512 + t] = hi;
}

// ---------------------------------------------------------------------------
// Convert x (fp32 [Mrows][256]) -> bf16 split [hi | lo | hi], row-major.
// One thread per (m, 8-feature group); 3 x uint4 coalesced stores.
// ---------------------------------------------------------------------------
__global__ __launch_bounds__(256) void convA_kernel(const float* __restrict__ src)
{
    int gid = blockIdx.x * 256 + threadIdx.x;      // Mrows*32 = 524288
    int m = gid >> 5, kg = gid & 31, k0 = kg * 8;
    const float4* s4 = (const float4*)src + (size_t)m * 64 + kg * 2;
    float4 f0 = s4[0], f1 = s4[1];
    float f[8] = {f0.x, f0.y, f0.z, f0.w, f1.x, f1.y, f1.z, f1.w};
    union { unsigned short h[8]; uint4 v; } hi, lo;
#pragma unroll
    for (int j = 0; j < 8; j++) {
        __nv_bfloat16 h = __float2bfloat16_rn(f[j]);
        hi.h[j] = __bfloat16_as_ushort(h);
        lo.h[j] = __bfloat16_as_ushort(__float2bfloat16_rn(f[j] - __bfloat162float(h)));
    }
    __nv_bfloat16* o = g_Aself + (size_t)m * Ktot;
    *(uint4*)(o + k0)       = hi.v;
    *(uint4*)(o + 256 + k0) = lo.v;
    *(uint4*)(o + 512 + k0) = hi.v;
}

// ---------------------------------------------------------------------------
// Convert W (fp32 [256][256]) -> bf16 split [hi | hi | lo], row-major.
// ---------------------------------------------------------------------------
__global__ __launch_bounds__(256) void convW_kernel(const float* __restrict__ w, int g)
{
    int gid = blockIdx.x * 256 + threadIdx.x;      // 8192
    int o_ = gid >> 5, kg = gid & 31, k0 = kg * 8;
    const float4* s4 = (const float4*)w + (size_t)o_ * 64 + kg * 2;
    float4 f0 = s4[0], f1 = s4[1];
    float f[8] = {f0.x, f0.y, f0.z, f0.w, f1.x, f1.y, f1.z, f1.w};
    union { unsigned short h[8]; uint4 v; } hi, lo;
#pragma unroll
    for (int j = 0; j < 8; j++) {
        __nv_bfloat16 h = __float2bfloat16_rn(f[j]);
        hi.h[j] = __bfloat16_as_ushort(h);
        lo.h[j] = __bfloat16_as_ushort(__float2bfloat16_rn(f[j] - __bfloat162float(h)));
    }
    __nv_bfloat16* dst = g_Wbf[g] + (size_t)o_ * Ktot;
    *(uint4*)(dst + k0)       = hi.v;
    *(uint4*)(dst + 256 + k0) = hi.v;
    *(uint4*)(dst + 512 + k0) = lo.v;
}

// ---------------------------------------------------------------------------
// bf16 GEMM via mma.sync (HMMA): C[m, coloff+o] = sum_k A[m,k]*W[o,k] + bias[o]
// BM=64, BN=128, BK=32, 256 threads (8 warps, 2m x 4n), warp tile 32x32.
// cp.async double-buffered smem; ldmatrix x4 (A) / x2 (B); padded stride 40.
// ---------------------------------------------------------------------------
#define BM 64
#define BN 128
#define BK 32
#define SLD2 40      // bf16 elements per smem row (80B -> conflict-free ldmatrix)
#define KIT (Ktot / BK)   // 24

__device__ __forceinline__ uint32_t smem_u32(const void* p) {
    uint32_t a;
    asm("{ .reg .u64 t; cvta.to.shared.u64 t, %1; cvt.u32.u64 %0, t; }" : "=r"(a) : "l"(p));
    return a;
}
#define CP16(dst, src) \
    asm volatile("cp.async.cg.shared.global [%0], [%1], 16;" :: "r"(dst), "l"(src))
#define CP_COMMIT() asm volatile("cp.async.commit_group;")
#define CP_WAIT1()  asm volatile("cp.async.wait_group 1;")

__global__ __launch_bounds__(256) void gemm_mma_kernel(
    const __nv_bfloat16* __restrict__ Abf, const __nv_bfloat16* __restrict__ Wbf,
    const float* __restrict__ bias, float* __restrict__ C, int coloff)
{
    __shared__ __align__(16) __nv_bfloat16 As[2][BM * SLD2];
    __shared__ __align__(16) __nv_bfloat16 Bs[2][BN * SLD2];

    const int tid = threadIdx.x;
    const int lane = tid & 31, wid = tid >> 5;
    const int wm = wid >> 2, wn = wid & 3;          // 2 x 4 warp grid
    const int m0 = blockIdx.x * BM, n0 = blockIdx.y * BN;

    // --- cp.async source/dest (16B granules) ---
    const int lrow = tid >> 2;                      // 0..63
    const int lch  = (tid & 3) * 8;                 // bf16 col of 16B chunk
    const __nv_bfloat16* Asrc  = Abf + (size_t)(m0 + lrow) * Ktot + lch;
    const __nv_bfloat16* Bsrc0 = Wbf + (size_t)(n0 + lrow) * Ktot + lch;
    const __nv_bfloat16* Bsrc1 = Wbf + (size_t)(n0 + 64 + lrow) * Ktot + lch;
    uint32_t dA[2], dB0[2], dB1[2];
#pragma unroll
    for (int st = 0; st < 2; st++) {
        dA[st]  = smem_u32(&As[st][lrow * SLD2 + lch]);
        dB0[st] = smem_u32(&Bs[st][lrow * SLD2 + lch]);
        dB1[st] = smem_u32(&Bs[st][(64 + lrow) * SLD2 + lch]);
    }

    // --- ldmatrix per-thread base addresses ---
    uint32_t aAddr[2], bAddr[2];
    {
        int arow = wm * 32 + (lane & 15);
        int acol = (lane >> 4) * 8;
        int l16  = lane & 15;
        int brow = wn * 32 + (l16 & 7);
        int bcol = (l16 >> 3) * 8;
#pragma unroll
        for (int st = 0; st < 2; st++) {
            aAddr[st] = smem_u32(&As[st][arow * SLD2 + acol]);
            bAddr[st] = smem_u32(&Bs[st][brow * SLD2 + bcol]);
        }
    }

    float d[2][4][4];
#pragma unroll
    for (int mi = 0; mi < 2; mi++)
#pragma unroll
        for (int ni = 0; ni < 4; ni++)
#pragma unroll
            for (int q = 0; q < 4; q++) d[mi][ni][q] = 0.0f;

    // preload stages 0,1
#pragma unroll
    for (int st = 0; st < 2; st++) {
        int k0 = st * BK;
        CP16(dA[st],  Asrc  + k0);
        CP16(dB0[st], Bsrc0 + k0);
        CP16(dB1[st], Bsrc1 + k0);
        CP_COMMIT();
    }

#pragma unroll 1
    for (int it = 0; it < KIT; it++) {
        const int st = it & 1;
        CP_WAIT1();
        __syncthreads();

#pragma unroll
        for (int s = 0; s < 2; s++) {               // two k16 steps
            uint32_t a[2][4], b[4][2];
#pragma unroll
            for (int mi = 0; mi < 2; mi++) {
                uint32_t addr = aAddr[st] + mi * (16 * SLD2 * 2) + s * 32;
                asm volatile("ldmatrix.sync.aligned.m8n8.x4.shared.b16 {%0,%1,%2,%3}, [%4];"
                             : "=r"(a[mi][0]), "=r"(a[mi][1]), "=r"(a[mi][2]), "=r"(a[mi][3])
                             : "r"(addr));
            }
#pragma unroll
            for (int ni = 0; ni < 4; ni++) {
                uint32_t addr = bAddr[st] + ni * (8 * SLD2 * 2) + s * 32;
                asm volatile("ldmatrix.sync.aligned.m8n8.x2.shared.b16 {%0,%1}, [%2];"
                             : "=r"(b[ni][0]), "=r"(b[ni][1]) : "r"(addr));
            }
#pragma unroll
            for (int mi = 0; mi < 2; mi++)
#pragma unroll
                for (int ni = 0; ni < 4; ni++)
                    asm volatile(
                        "mma.sync.aligned.m16n8k16.row.col.f32.bf16.bf16.f32 "
                        "{%0,%1,%2,%3}, {%4,%5,%6,%7}, {%8,%9}, {%0,%1,%2,%3};"
                        : "+f"(d[mi][ni][0]), "+f"(d[mi][ni][1]),
                          "+f"(d[mi][ni][2]), "+f"(d[mi][ni][3])
                        : "r"(a[mi][0]), "r"(a[mi][1]), "r"(a[mi][2]), "r"(a[mi][3]),
                          "r"(b[ni][0]), "r"(b[ni][1]));
        }
        __syncthreads();
        if (it + 2 < KIT) {
            int k0 = (it + 2) * BK;
            CP16(dA[st],  Asrc  + k0);
            CP16(dB0[st], Bsrc0 + k0);
            CP16(dB1[st], Bsrc1 + k0);
        }
        CP_COMMIT();   // commit even if empty to keep wait_group accounting simple
    }

    // epilogue: D frag -> C with bias
    const int quad = lane >> 2, tq = lane & 3;
#pragma unroll
    for (int mi = 0; mi < 2; mi++) {
        int row = m0 + wm * 32 + mi * 16 + quad;
#pragma unroll
        for (int ni = 0; ni < 4; ni++) {
            int col = n0 + wn * 32 + ni * 8 + tq * 2;
            float2 bv = *(const float2*)(bias + col);
            float2 v0 = make_float2(d[mi][ni][0] + bv.x, d[mi][ni][1] + bv.y);
            float2 v1 = make_float2(d[mi][ni][2] + bv.x, d[mi][ni][3] + bv.y);
            *(float2*)&C[(size_t)row * Cch + coloff + col] = v0;
            *(float2*)&C[(size_t)(row + 8) * Cch + coloff + col] = v1;
        }
    }
}

// ---------------------------------------------------------------------------
// Per-row L2 normalize + ReLU + BN stats. Warp-per-row, smem-staged stats.
// ---------------------------------------------------------------------------
#define NR 16   // rows per warp

__global__ __launch_bounds__(256) void norm_relu_stats_kernel(float* __restrict__ h)
{
    __shared__ float ssum[Cch], ssq[Cch];
    const int tid = threadIdx.x, lane = tid & 31, wid = tid >> 5;
    ssum[tid] = 0.f; ssq[tid] = 0.f;
    ssum[tid + 256] = 0.f; ssq[tid + 256] = 0.f;
    __syncthreads();

    float asum[4][4], asq[4][4];
#pragma unroll
    for (int q = 0; q < 4; q++)
#pragma unroll
        for (int j = 0; j < 4; j++) { asum[q][j] = 0.f; asq[q][j] = 0.f; }

    const int row0 = blockIdx.x * (8 * NR) + wid * NR;
#pragma unroll 1
    for (int r = 0; r < NR; r++) {
        float4* p = (float4*)(h + (size_t)(row0 + r) * Cch);
        float4 v[4];
#pragma unroll
        for (int q = 0; q < 4; q++) v[q] = p[lane + 32 * q];
        float s = 0.f;
#pragma unroll
        for (int q = 0; q < 4; q++)
            s += v[q].x * v[q].x + v[q].y * v[q].y + v[q].z * v[q].z + v[q].w * v[q].w;
#pragma unroll
        for (int o = 16; o; o >>= 1) s += __shfl_xor_sync(0xffffffffu, s, o);
        float inv = 1.0f / fmaxf(sqrtf(s), 1e-12f);
#pragma unroll
        for (int q = 0; q < 4; q++) {
            float u[4] = {v[q].x, v[q].y, v[q].z, v[q].w};
#pragma unroll
            for (int j = 0; j < 4; j++) {
                float t = fmaxf(u[j] * inv, 0.0f);
                u[j] = t;
                asum[q][j] += t;
                asq[q][j]  += t * t;
            }
            p[lane + 32 * q] = make_float4(u[0], u[1], u[2], u[3]);
        }
    }
#pragma unroll
    for (int q = 0; q < 4; q++)
#pragma unroll
        for (int j = 0; j < 4; j++) {
            int c = 4 * lane + 128 * q + j;
            atomicAdd(&ssum[c], asum[q][j]);
            atomicAdd(&ssq[c],  asq[q][j]);
        }
    __syncthreads();
    for (int c = tid; c < Cch; c += 256) {
        atomicAdd(&g_stats[c],       ssum[c]);
        atomicAdd(&g_stats[Cch + c], ssq[c]);
    }
}

// ---------------------------------------------------------------------------
// BN finalize + apply fused: each block recomputes scale/shift, applies chunk.
// ---------------------------------------------------------------------------
__global__ __launch_bounds__(256) void bn_apply_kernel(
    const float* __restrict__ gamma, const float* __restrict__ beta,
    float* __restrict__ h)
{
    __shared__ float sc[Cch], sh[Cch];
    const int tid = threadIdx.x;
    const float invM = 1.0f / (float)Mrows;
    for (int c = tid; c < Cch; c += 256) {
        float mu  = g_stats[c] * invM;
        float var = g_stats[Cch + c] * invM - mu * mu;
        float s   = gamma[c] * rsqrtf(var + 1e-5f);
        sc[c] = s;
        sh[c] = beta[c] - mu * s;
    }
    __syncthreads();
    size_t i0 = (size_t)blockIdx.x * 256 * 32;
#pragma unroll 4
    for (int u = 0; u < 32; u++) {
        size_t i = i0 + u * 256 + tid;       // float4 index
        float4 v = ((float4*)h)[i];
        int c = ((int)i << 2) & (Cch - 1);
        v.x = v.x * sc[c + 0] + sh[c + 0];
        v.y = v.y * sc[c + 1] + sh[c + 1];
        v.z = v.z * sc[c + 2] + sh[c + 2];
        v.w = v.w * sc[c + 3] + sh[c + 3];
        ((float4*)h)[i] = v;
    }
}

// ---------------------------------------------------------------------------
// Launch
// Inputs: x, idx_neib, Wx_w, Wx_b, Wn_w, Wn_b, gamma, beta
// ---------------------------------------------------------------------------
extern "C" void kernel_launch(void* const* d_in, const int* in_sizes, int n_in,
                              void* d_out, int out_size)
{
    const float* x     = (const float*)d_in[0];
    const int*   idx   = (const int*)  d_in[1];
    const float* Wx_w  = (const float*)d_in[2];
    const float* Wx_b  = (const float*)d_in[3];
    const float* Wn_w  = (const float*)d_in[4];
    const float* Wn_b  = (const float*)d_in[5];
    const float* gamma = (const float*)d_in[6];
    const float* beta  = (const float*)d_in[7];
    float* out = (float*)d_out;

    static cudaStream_t s2 = nullptr;
    static cudaEvent_t ev_fork = nullptr, ev_join = nullptr;
    static int stream_ok = -1;
    if (stream_ok < 0) {
        stream_ok = (cudaStreamCreateWithFlags(&s2, cudaStreamNonBlocking) == cudaSuccess &&
                     cudaEventCreateWithFlags(&ev_fork, cudaEventDisableTiming) == cudaSuccess &&
                     cudaEventCreateWithFlags(&ev_join, cudaEventDisableTiming) == cudaSuccess)
                        ? 1 : 0;
    }

    __nv_bfloat16* Wself; cudaGetSymbolAddress((void**)&Wself, g_Wbf);  // [0]
    __nv_bfloat16* Wneib = Wself + 256 * Ktot;                          // [1]
    __nv_bfloat16* Aself; cudaGetSymbolAddress((void**)&Aself, g_Aself);
    __nv_bfloat16* Aneib; cudaGetSymbolAddress((void**)&Aneib, g_Aneib);

    dim3 ggrid(Mrows / BM, 2);   // 256 x 2

    zero_stats_kernel<<<2, 512>>>();
    convW_kernel<<<32, 256>>>(Wx_w, 0);
    convW_kernel<<<32, 256>>>(Wn_w, 1);

    if (stream_ok) {
        cudaEventRecord(ev_fork, 0);
        cudaStreamWaitEvent(s2, ev_fork, 0);
        // branch B: gather (fused bf16 split) -> neighbor GEMM
        gather_mean_bf16_kernel<<<dim3(Nn, Bc), Fin, 0, s2>>>(x, idx);
        gemm_mma_kernel<<<ggrid, 256, 0, s2>>>(Aneib, Wneib, Wn_b, out, 256);
        cudaEventRecord(ev_join, s2);
        // branch A: convert x -> self GEMM
        convA_kernel<<<2048, 256>>>(x);
        gemm_mma_kernel<<<ggrid, 256>>>(Aself, Wself, Wx_b, out, 0);
        cudaStreamWaitEvent(0, ev_join, 0);
    } else {
        gather_mean_bf16_kernel<<<dim3(Nn, Bc), Fin>>>(x, idx);
        convA_kernel<<<2048, 256>>>(x);
        gemm_mma_kernel<<<ggrid, 256>>>(Aself, Wself, Wx_b, out, 0);
        gemm_mma_kernel<<<ggrid, 256>>>(Aneib, Wneib, Wn_b, out, 256);
    }

    norm_relu_stats_kernel<<<Mrows / (8 * NR), 256>>>(out);
    bn_apply_kernel<<<256, 256>>>(gamma, beta, out);
}

// round 5
// speedup vs baseline: 1.6704x; 1.1187x over previous
#include <cuda_runtime.h>
#include <cuda_bf16.h>
#include <cstdint>

// Problem constants
#define Bc   8
#define Nn   2048
#define Kn   32
#define Fin  256
#define Cch  512
#define Mrows 16384
#define Ktot 768            // 3-term bf16 split: [hi | lo | hi] x [hi | hi | lo]

// ---------------------------------------------------------------------------
// Device-global scratch (no allocations allowed)
// ---------------------------------------------------------------------------
__device__ __align__(16) __nv_bfloat16 g_Aself[Mrows * Ktot];   // 25.2 MB
__device__ __align__(16) __nv_bfloat16 g_Aneib[Mrows * Ktot];   // 25.2 MB
__device__ __align__(16) __nv_bfloat16 g_Wbf[2][256 * Ktot];    // 2 x 393 KB
__device__ float g_stats[2 * Cch];

// ---------------------------------------------------------------------------
// Zero BN stats
// ---------------------------------------------------------------------------
__global__ void zero_stats_kernel() {
    int i = blockIdx.x * blockDim.x + threadIdx.x;
    if (i < 2 * Cch) g_stats[i] = 0.0f;
}

// ---------------------------------------------------------------------------
// bf16 hi/lo split of a float4 -> two 8B packets
// ---------------------------------------------------------------------------
__device__ __forceinline__ void split4(float4 m, uint2& hv, uint2& lv) {
    float f[4] = {m.x, m.y, m.z, m.w};
    unsigned short h[4], l[4];
#pragma unroll
    for (int j = 0; j < 4; j++) {
        __nv_bfloat16 hb = __float2bfloat16_rn(f[j]);
        h[j] = __bfloat16_as_ushort(hb);
        l[j] = __bfloat16_as_ushort(__float2bfloat16_rn(f[j] - __bfloat162float(hb)));
    }
    hv = make_uint2((uint32_t)h[0] | ((uint32_t)h[1] << 16),
                    (uint32_t)h[2] | ((uint32_t)h[3] << 16));
    lv = make_uint2((uint32_t)l[0] | ((uint32_t)l[1] << 16),
                    (uint32_t)l[2] | ((uint32_t)l[3] << 16));
}

// ---------------------------------------------------------------------------
// Gather-mean, float4-vectorized, fused bf16 split output.
// One block per n; 256 threads = 64 float4-lanes x (2 batches each of 4 groups).
// Thread t: f4 = t&63, handles batches bq and bq+4 (bq = t>>6).
// 2 LDG.128 per neighbor per thread; idx loaded once per n.
// ---------------------------------------------------------------------------
__global__ __launch_bounds__(256) void gather_mean_bf16_kernel(
    const float* __restrict__ x, const int* __restrict__ idx)
{
    __shared__ int sidx[Kn];
    const int n = blockIdx.x, t = threadIdx.x;
    if (t < Kn) sidx[t] = idx[n * Kn + t];
    __syncthreads();

    const int f4 = t & 63;
    const int bq = t >> 6;             // 0..3 -> batches bq, bq+4
    const float4* xb0 = (const float4*)x + (size_t)bq * Nn * 64 + f4;
    const float4* xb1 = xb0 + (size_t)4 * Nn * 64;

    float4 a0e = {0,0,0,0}, a0o = {0,0,0,0}, a1e = {0,0,0,0}, a1o = {0,0,0,0};
#pragma unroll
    for (int k = 0; k < Kn; k += 2) {
        int r0 = sidx[k] * 64, r1 = sidx[k + 1] * 64;
        float4 v00 = xb0[r0], v01 = xb0[r1];
        float4 v10 = xb1[r0], v11 = xb1[r1];
        a0e.x += v00.x; a0e.y += v00.y; a0e.z += v00.z; a0e.w += v00.w;
        a0o.x += v01.x; a0o.y += v01.y; a0o.z += v01.z; a0o.w += v01.w;
        a1e.x += v10.x; a1e.y += v10.y; a1e.z += v10.z; a1e.w += v10.w;
        a1o.x += v11.x; a1o.y += v11.y; a1o.z += v11.z; a1o.w += v11.w;
    }
    const float s = 1.0f / Kn;
    float4 m0 = make_float4((a0e.x + a0o.x) * s, (a0e.y + a0o.y) * s,
                            (a0e.z + a0o.z) * s, (a0e.w + a0o.w) * s);
    float4 m1 = make_float4((a1e.x + a1o.x) * s, (a1e.y + a1o.y) * s,
                            (a1e.z + a1o.z) * s, (a1e.w + a1o.w) * s);

    uint2 hv, lv;
    split4(m0, hv, lv);
    {
        __nv_bfloat16* o = g_Aneib + ((size_t)bq * Nn + n) * Ktot + f4 * 4;
        *(uint2*)(o)       = hv;
        *(uint2*)(o + 256) = lv;
        *(uint2*)(o + 512) = hv;
    }
    split4(m1, hv, lv);
    {
        __nv_bfloat16* o = g_Aneib + ((size_t)(bq + 4) * Nn + n) * Ktot + f4 * 4;
        *(uint2*)(o)       = hv;
        *(uint2*)(o + 256) = lv;
        *(uint2*)(o + 512) = hv;
    }
}

// ---------------------------------------------------------------------------
// Convert x (fp32 [Mrows][256]) -> bf16 split [hi | lo | hi], row-major.
// ---------------------------------------------------------------------------
__global__ __launch_bounds__(256) void convA_kernel(const float* __restrict__ src)
{
    int gid = blockIdx.x * 256 + threadIdx.x;      // Mrows*32
    int m = gid >> 5, kg = gid & 31, k0 = kg * 8;
    const float4* s4 = (const float4*)src + (size_t)m * 64 + kg * 2;
    float4 f0 = s4[0], f1 = s4[1];
    float f[8] = {f0.x, f0.y, f0.z, f0.w, f1.x, f1.y, f1.z, f1.w};
    union { unsigned short h[8]; uint4 v; } hi, lo;
#pragma unroll
    for (int j = 0; j < 8; j++) {
        __nv_bfloat16 h = __float2bfloat16_rn(f[j]);
        hi.h[j] = __bfloat16_as_ushort(h);
        lo.h[j] = __bfloat16_as_ushort(__float2bfloat16_rn(f[j] - __bfloat162float(h)));
    }
    __nv_bfloat16* o = g_Aself + (size_t)m * Ktot;
    *(uint4*)(o + k0)       = hi.v;
    *(uint4*)(o + 256 + k0) = lo.v;
    *(uint4*)(o + 512 + k0) = hi.v;
}

// ---------------------------------------------------------------------------
// Convert W (fp32 [256][256]) -> bf16 split [hi | hi | lo], row-major.
// ---------------------------------------------------------------------------
__global__ __launch_bounds__(256) void convW_kernel(const float* __restrict__ w, int g)
{
    int gid = blockIdx.x * 256 + threadIdx.x;      // 8192
    int o_ = gid >> 5, kg = gid & 31, k0 = kg * 8;
    const float4* s4 = (const float4*)w + (size_t)o_ * 64 + kg * 2;
    float4 f0 = s4[0], f1 = s4[1];
    float f[8] = {f0.x, f0.y, f0.z, f0.w, f1.x, f1.y, f1.z, f1.w};
    union { unsigned short h[8]; uint4 v; } hi, lo;
#pragma unroll
    for (int j = 0; j < 8; j++) {
        __nv_bfloat16 h = __float2bfloat16_rn(f[j]);
        hi.h[j] = __bfloat16_as_ushort(h);
        lo.h[j] = __bfloat16_as_ushort(__float2bfloat16_rn(f[j] - __bfloat162float(h)));
    }
    __nv_bfloat16* dst = g_Wbf[g] + (size_t)o_ * Ktot;
    *(uint4*)(dst + k0)       = hi.v;
    *(uint4*)(dst + 256 + k0) = hi.v;
    *(uint4*)(dst + 512 + k0) = lo.v;
}

// ---------------------------------------------------------------------------
// bf16 GEMM via mma.sync (HMMA): C[m, coloff+o] = sum_k A[m,k]*W[o,k] + bias[o]
// BM=64, BN=128, BK=64, 256 threads (2m x 4n warps), warp tile 32x32.
// 12 iterations (half the barriers of BK=32); cp.async double-buffered
// dynamic smem (55.3 KB); ldmatrix x4 (A) / x2 (B); padded stride 72.
// ---------------------------------------------------------------------------
#define BM 64
#define BN 128
#define BK 64
#define SLD 72                // bf16 per smem row (144B): conflict-free ldmatrix
#define KIT (Ktot / BK)       // 12
#define A_ST_ELT (BM * SLD)   // 4608
#define B_ST_ELT (BN * SLD)   // 9216
#define A_ST_B   (A_ST_ELT * 2)
#define B_ST_B   (B_ST_ELT * 2)
#define GEMM_SMEM ((A_ST_ELT + B_ST_ELT) * 2 * 2)   // 55296 bytes

__device__ __forceinline__ uint32_t smem_u32(const void* p) {
    uint32_t a;
    asm("{ .reg .u64 t; cvta.to.shared.u64 t, %1; cvt.u32.u64 %0, t; }" : "=r"(a) : "l"(p));
    return a;
}
#define CP16(dst, src) \
    asm volatile("cp.async.cg.shared.global [%0], [%1], 16;" :: "r"(dst), "l"(src))
#define CP_COMMIT() asm volatile("cp.async.commit_group;")
#define CP_WAIT1()  asm volatile("cp.async.wait_group 1;")

__global__ __launch_bounds__(256) void gemm_mma_kernel(
    const __nv_bfloat16* __restrict__ Abf, const __nv_bfloat16* __restrict__ Wbf,
    const float* __restrict__ bias, float* __restrict__ C, int coloff)
{
    extern __shared__ __align__(16) __nv_bfloat16 sm[];
    __nv_bfloat16* As0 = sm;                       // stages: +A_ST_ELT
    __nv_bfloat16* Bs0 = sm + 2 * A_ST_ELT;        // stages: +B_ST_ELT

    const int tid = threadIdx.x;
    const int lane = tid & 31, wid = tid >> 5;
    const int wm = wid >> 2, wn = wid & 3;          // 2 x 4 warp grid
    const int m0 = blockIdx.x * BM, n0 = blockIdx.y * BN;

    // --- cp.async: A 512 chunks (2/thread), B 1024 chunks (4/thread) ---
    const __nv_bfloat16* aSrc[2];
    const __nv_bfloat16* bSrc[4];
    uint32_t dA0[2], dB0[4];
#pragma unroll
    for (int i = 0; i < 2; i++) {
        int c = tid + 256 * i, row = c >> 3, col = (c & 7) * 8;
        aSrc[i] = Abf + (size_t)(m0 + row) * Ktot + col;
        dA0[i] = smem_u32(&As0[row * SLD + col]);
    }
#pragma unroll
    for (int i = 0; i < 4; i++) {
        int c = tid + 256 * i, row = c >> 3, col = (c & 7) * 8;
        bSrc[i] = Wbf + (size_t)(n0 + row) * Ktot + col;
        dB0[i] = smem_u32(&Bs0[row * SLD + col]);
    }

    // --- ldmatrix per-thread base addresses (stage 0) ---
    uint32_t aAddr0, bAddr0;
    {
        int arow = wm * 32 + (lane & 15);
        int acol = (lane >> 4) * 8;
        int l16  = lane & 15;
        int brow = wn * 32 + (l16 & 7);
        int bcol = (l16 >> 3) * 8;
        aAddr0 = smem_u32(&As0[arow * SLD + acol]);
        bAddr0 = smem_u32(&Bs0[brow * SLD + bcol]);
    }

    float d[2][4][4];
#pragma unroll
    for (int mi = 0; mi < 2; mi++)
#pragma unroll
        for (int ni = 0; ni < 4; ni++)
#pragma unroll
            for (int q = 0; q < 4; q++) d[mi][ni][q] = 0.0f;

    // preload stages 0,1
#pragma unroll
    for (int st = 0; st < 2; st++) {
        int k0 = st * BK;
#pragma unroll
        for (int i = 0; i < 2; i++) CP16(dA0[i] + st * A_ST_B, aSrc[i] + k0);
#pragma unroll
        for (int i = 0; i < 4; i++) CP16(dB0[i] + st * B_ST_B, bSrc[i] + k0);
        CP_COMMIT();
    }

#pragma unroll 1
    for (int it = 0; it < KIT; it++) {
        const int st = it & 1;
        CP_WAIT1();
        __syncthreads();

        const uint32_t aA = aAddr0 + st * A_ST_B;
        const uint32_t bA = bAddr0 + st * B_ST_B;
#pragma unroll
        for (int s = 0; s < 4; s++) {               // four k16 steps
            uint32_t a[2][4], b[4][2];
#pragma unroll
            for (int mi = 0; mi < 2; mi++) {
                uint32_t addr = aA + mi * (16 * SLD * 2) + s * 32;
                asm volatile("ldmatrix.sync.aligned.m8n8.x4.shared.b16 {%0,%1,%2,%3}, [%4];"
                             : "=r"(a[mi][0]), "=r"(a[mi][1]), "=r"(a[mi][2]), "=r"(a[mi][3])
                             : "r"(addr));
            }
#pragma unroll
            for (int ni = 0; ni < 4; ni++) {
                uint32_t addr = bA + ni * (8 * SLD * 2) + s * 32;
                asm volatile("ldmatrix.sync.aligned.m8n8.x2.shared.b16 {%0,%1}, [%2];"
                             : "=r"(b[ni][0]), "=r"(b[ni][1]) : "r"(addr));
            }
#pragma unroll
            for (int mi = 0; mi < 2; mi++)
#pragma unroll
                for (int ni = 0; ni < 4; ni++)
                    asm volatile(
                        "mma.sync.aligned.m16n8k16.row.col.f32.bf16.bf16.f32 "
                        "{%0,%1,%2,%3}, {%4,%5,%6,%7}, {%8,%9}, {%0,%1,%2,%3};"
                        : "+f"(d[mi][ni][0]), "+f"(d[mi][ni][1]),
                          "+f"(d[mi][ni][2]), "+f"(d[mi][ni][3])
                        : "r"(a[mi][0]), "r"(a[mi][1]), "r"(a[mi][2]), "r"(a[mi][3]),
                          "r"(b[ni][0]), "r"(b[ni][1]));
        }
        __syncthreads();
        if (it + 2 < KIT) {
            int k0 = (it + 2) * BK;
#pragma unroll
            for (int i = 0; i < 2; i++) CP16(dA0[i] + st * A_ST_B, aSrc[i] + k0);
#pragma unroll
            for (int i = 0; i < 4; i++) CP16(dB0[i] + st * B_ST_B, bSrc[i] + k0);
        }
        CP_COMMIT();   // commit even if empty to keep wait_group accounting simple
    }

    // epilogue: D frag -> C with bias
    const int quad = lane >> 2, tq = lane & 3;
#pragma unroll
    for (int mi = 0; mi < 2; mi++) {
        int row = m0 + wm * 32 + mi * 16 + quad;
#pragma unroll
        for (int ni = 0; ni < 4; ni++) {
            int col = n0 + wn * 32 + ni * 8 + tq * 2;
            float2 bv = *(const float2*)(bias + col);
            float2 v0 = make_float2(d[mi][ni][0] + bv.x, d[mi][ni][1] + bv.y);
            float2 v1 = make_float2(d[mi][ni][2] + bv.x, d[mi][ni][3] + bv.y);
            *(float2*)&C[(size_t)row * Cch + coloff + col] = v0;
            *(float2*)&C[(size_t)(row + 8) * Cch + coloff + col] = v1;
        }
    }
}

// ---------------------------------------------------------------------------
// Per-row L2 normalize + ReLU + BN stats. Warp-per-row, smem-staged stats.
// ---------------------------------------------------------------------------
#define NR 16   // rows per warp

__global__ __launch_bounds__(256) void norm_relu_stats_kernel(float* __restrict__ h)
{
    __shared__ float ssum[Cch], ssq[Cch];
    const int tid = threadIdx.x, lane = tid & 31, wid = tid >> 5;
    ssum[tid] = 0.f; ssq[tid] = 0.f;
    ssum[tid + 256] = 0.f; ssq[tid + 256] = 0.f;
    __syncthreads();

    float asum[4][4], asq[4][4];
#pragma unroll
    for (int q = 0; q < 4; q++)
#pragma unroll
        for (int j = 0; j < 4; j++) { asum[q][j] = 0.f; asq[q][j] = 0.f; }

    const int row0 = blockIdx.x * (8 * NR) + wid * NR;
#pragma unroll 1
    for (int r = 0; r < NR; r++) {
        float4* p = (float4*)(h + (size_t)(row0 + r) * Cch);
        float4 v[4];
#pragma unroll
        for (int q = 0; q < 4; q++) v[q] = p[lane + 32 * q];
        float s = 0.f;
#pragma unroll
        for (int q = 0; q < 4; q++)
            s += v[q].x * v[q].x + v[q].y * v[q].y + v[q].z * v[q].z + v[q].w * v[q].w;
#pragma unroll
        for (int o = 16; o; o >>= 1) s += __shfl_xor_sync(0xffffffffu, s, o);
        float inv = 1.0f / fmaxf(sqrtf(s), 1e-12f);
#pragma unroll
        for (int q = 0; q < 4; q++) {
            float u[4] = {v[q].x, v[q].y, v[q].z, v[q].w};
#pragma unroll
            for (int j = 0; j < 4; j++) {
                float t = fmaxf(u[j] * inv, 0.0f);
                u[j] = t;
                asum[q][j] += t;
                asq[q][j]  += t * t;
            }
            p[lane + 32 * q] = make_float4(u[0], u[1], u[2], u[3]);
        }
    }
#pragma unroll
    for (int q = 0; q < 4; q++)
#pragma unroll
        for (int j = 0; j < 4; j++) {
            int c = 4 * lane + 128 * q + j;
            atomicAdd(&ssum[c], asum[q][j]);
            atomicAdd(&ssq[c],  asq[q][j]);
        }
    __syncthreads();
    for (int c = tid; c < Cch; c += 256) {
        atomicAdd(&g_stats[c],       ssum[c]);
        atomicAdd(&g_stats[Cch + c], ssq[c]);
    }
}

// ---------------------------------------------------------------------------
// BN finalize + apply fused: each block recomputes scale/shift, applies chunk.
// ---------------------------------------------------------------------------
__global__ __launch_bounds__(256) void bn_apply_kernel(
    const float* __restrict__ gamma, const float* __restrict__ beta,
    float* __restrict__ h)
{
    __shared__ float sc[Cch], sh[Cch];
    const int tid = threadIdx.x;
    const float invM = 1.0f / (float)Mrows;
    for (int c = tid; c < Cch; c += 256) {
        float mu  = g_stats[c] * invM;
        float var = g_stats[Cch + c] * invM - mu * mu;
        float s   = gamma[c] * rsqrtf(var + 1e-5f);
        sc[c] = s;
        sh[c] = beta[c] - mu * s;
    }
    __syncthreads();
    size_t i0 = (size_t)blockIdx.x * 256 * 32;
#pragma unroll 4
    for (int u = 0; u < 32; u++) {
        size_t i = i0 + u * 256 + tid;       // float4 index
        float4 v = ((float4*)h)[i];
        int c = ((int)i << 2) & (Cch - 1);
        v.x = v.x * sc[c + 0] + sh[c + 0];
        v.y = v.y * sc[c + 1] + sh[c + 1];
        v.z = v.z * sc[c + 2] + sh[c + 2];
        v.w = v.w * sc[c + 3] + sh[c + 3];
        ((float4*)h)[i] = v;
    }
}

// ---------------------------------------------------------------------------
// Launch
// Inputs: x, idx_neib, Wx_w, Wx_b, Wn_w, Wn_b, gamma, beta
// ---------------------------------------------------------------------------
extern "C" void kernel_launch(void* const* d_in, const int* in_sizes, int n_in,
                              void* d_out, int out_size)
{
    const float* x     = (const float*)d_in[0];
    const int*   idx   = (const int*)  d_in[1];
    const float* Wx_w  = (const float*)d_in[2];
    const float* Wx_b  = (const float*)d_in[3];
    const float* Wn_w  = (const float*)d_in[4];
    const float* Wn_b  = (const float*)d_in[5];
    const float* gamma = (const float*)d_in[6];
    const float* beta  = (const float*)d_in[7];
    float* out = (float*)d_out;

    static cudaStream_t s2 = nullptr;
    static cudaEvent_t ev_fork = nullptr, ev_join = nullptr;
    static int stream_ok = -1;
    if (stream_ok < 0) {
        bool ok = cudaFuncSetAttribute(gemm_mma_kernel,
                     cudaFuncAttributeMaxDynamicSharedMemorySize, GEMM_SMEM) == cudaSuccess;
        ok = ok && cudaStreamCreateWithFlags(&s2, cudaStreamNonBlocking) == cudaSuccess;
        ok = ok && cudaEventCreateWithFlags(&ev_fork, cudaEventDisableTiming) == cudaSuccess;
        ok = ok && cudaEventCreateWithFlags(&ev_join, cudaEventDisableTiming) == cudaSuccess;
        stream_ok = ok ? 1 : 0;
    }

    __nv_bfloat16* Wself; cudaGetSymbolAddress((void**)&Wself, g_Wbf);  // [0]
    __nv_bfloat16* Wneib = Wself + 256 * Ktot;                          // [1]
    __nv_bfloat16* Aself; cudaGetSymbolAddress((void**)&Aself, g_Aself);
    __nv_bfloat16* Aneib; cudaGetSymbolAddress((void**)&Aneib, g_Aneib);

    dim3 ggrid(Mrows / BM, 2);   // 256 x 2

    zero_stats_kernel<<<2, 512>>>();
    convW_kernel<<<32, 256>>>(Wx_w, 0);
    convW_kernel<<<32, 256>>>(Wn_w, 1);

    if (stream_ok) {
        cudaEventRecord(ev_fork, 0);
        cudaStreamWaitEvent(s2, ev_fork, 0);
        // branch B: gather (fused bf16 split) -> neighbor GEMM
        gather_mean_bf16_kernel<<<Nn, 256, 0, s2>>>(x, idx);
        gemm_mma_kernel<<<ggrid, 256, GEMM_SMEM, s2>>>(Aneib, Wneib, Wn_b, out, 256);
        cudaEventRecord(ev_join, s2);
        // branch A: convert x -> self GEMM
        convA_kernel<<<2048, 256>>>(x);
        gemm_mma_kernel<<<ggrid, 256, GEMM_SMEM>>>(Aself, Wself, Wx_b, out, 0);
        cudaStreamWaitEvent(0, ev_join, 0);
    } else {
        gather_mean_bf16_kernel<<<Nn, 256>>>(x, idx);
        convA_kernel<<<2048, 256>>>(x);
        gemm_mma_kernel<<<ggrid, 256, GEMM_SMEM>>>(Aself, Wself, Wx_b, out, 0);
        gemm_mma_kernel<<<ggrid, 256, GEMM_SMEM>>>(Aneib, Wneib, Wn_b, out, 256);
    }

    norm_relu_stats_kernel<<<Mrows / (8 * NR), 256>>>(out);
    bn_apply_kernel<<<256, 256>>>(gamma, beta, out);
}

// round 6
// speedup vs baseline: 1.7318x; 1.0368x over previous
#include <cuda_runtime.h>
#include <cuda_bf16.h>
#include <cstdint>

// Problem constants
#define Bc   8
#define Nn   2048
#define Kn   32
#define Fin  256
#define Cch  512
#define Mrows 16384
#define Kimg 512            // physical image: [hi(256) | lo(256)]
#define KIT  12             // logical K chunks of 64 (A: hi,lo,hi ; W: hi,hi,lo)

// ---------------------------------------------------------------------------
// Device-global scratch (no allocations allowed)
// ---------------------------------------------------------------------------
__device__ __align__(16) __nv_bfloat16 g_Aself[Mrows * Kimg];   // 16.8 MB
__device__ __align__(16) __nv_bfloat16 g_Aneib[Mrows * Kimg];   // 16.8 MB
__device__ __align__(16) __nv_bfloat16 g_Wbf[2][256 * Kimg];    // 2 x 262 KB
__device__ float g_stats[2 * Cch];
__device__ float g_invn[Mrows];

// ---------------------------------------------------------------------------
// Zero BN stats
// ---------------------------------------------------------------------------
__global__ void zero_stats_kernel() {
    int i = blockIdx.x * blockDim.x + threadIdx.x;
    if (i < 2 * Cch) g_stats[i] = 0.0f;
}

// ---------------------------------------------------------------------------
// bf16 hi/lo split of a float4 -> two 8B packets
// ---------------------------------------------------------------------------
__device__ __forceinline__ void split4(float4 m, uint2& hv, uint2& lv) {
    float f[4] = {m.x, m.y, m.z, m.w};
    unsigned short h[4], l[4];
#pragma unroll
    for (int j = 0; j < 4; j++) {
        __nv_bfloat16 hb = __float2bfloat16_rn(f[j]);
        h[j] = __bfloat16_as_ushort(hb);
        l[j] = __bfloat16_as_ushort(__float2bfloat16_rn(f[j] - __bfloat162float(hb)));
    }
    hv = make_uint2((uint32_t)h[0] | ((uint32_t)h[1] << 16),
                    (uint32_t)h[2] | ((uint32_t)h[3] << 16));
    lv = make_uint2((uint32_t)l[0] | ((uint32_t)l[1] << 16),
                    (uint32_t)l[2] | ((uint32_t)l[3] << 16));
}

// ---------------------------------------------------------------------------
// Gather-mean, float4-vectorized, fused bf16 split output.
// One block per n; 512 threads = 64 float4-lanes x 8 batches (1 per thread).
// Low register count -> high occupancy; 32 independent LDG.128 per thread.
// ---------------------------------------------------------------------------
__global__ __launch_bounds__(512) void gather_mean_bf16_kernel(
    const float* __restrict__ x, const int* __restrict__ idx)
{
    __shared__ int sidx[Kn];
    const int n = blockIdx.x, t = threadIdx.x;
    if (t < Kn) sidx[t] = idx[n * Kn + t];
    __syncthreads();

    const int f4 = t & 63;
    const int b  = t >> 6;             // 0..7
    const float4* xb = (const float4*)x + (size_t)b * Nn * 64 + f4;

    float4 ae = {0,0,0,0}, ao = {0,0,0,0};
#pragma unroll
    for (int k = 0; k < Kn; k += 2) {
        float4 v0 = xb[sidx[k] * 64];
        float4 v1 = xb[sidx[k + 1] * 64];
        ae.x += v0.x; ae.y += v0.y; ae.z += v0.z; ae.w += v0.w;
        ao.x += v1.x; ao.y += v1.y; ao.z += v1.z; ao.w += v1.w;
    }
    const float s = 1.0f / Kn;
    float4 m = make_float4((ae.x + ao.x) * s, (ae.y + ao.y) * s,
                           (ae.z + ao.z) * s, (ae.w + ao.w) * s);
    uint2 hv, lv;
    split4(m, hv, lv);
    __nv_bfloat16* o = g_Aneib + ((size_t)b * Nn + n) * Kimg + f4 * 4;
    *(uint2*)(o)       = hv;
    *(uint2*)(o + 256) = lv;
}

// ---------------------------------------------------------------------------
// Convert x (fp32 [Mrows][256]) -> bf16 split image [hi | lo], row-major.
// ---------------------------------------------------------------------------
__global__ __launch_bounds__(256) void convA_kernel(const float* __restrict__ src)
{
    int gid = blockIdx.x * 256 + threadIdx.x;      // Mrows*32
    int m = gid >> 5, kg = gid & 31, k0 = kg * 8;
    const float4* s4 = (const float4*)src + (size_t)m * 64 + kg * 2;
    float4 f0 = s4[0], f1 = s4[1];
    float f[8] = {f0.x, f0.y, f0.z, f0.w, f1.x, f1.y, f1.z, f1.w};
    union { unsigned short h[8]; uint4 v; } hi, lo;
#pragma unroll
    for (int j = 0; j < 8; j++) {
        __nv_bfloat16 h = __float2bfloat16_rn(f[j]);
        hi.h[j] = __bfloat16_as_ushort(h);
        lo.h[j] = __bfloat16_as_ushort(__float2bfloat16_rn(f[j] - __bfloat162float(h)));
    }
    __nv_bfloat16* o = g_Aself + (size_t)m * Kimg;
    *(uint4*)(o + k0)       = hi.v;
    *(uint4*)(o + 256 + k0) = lo.v;
}

// ---------------------------------------------------------------------------
// Convert W (fp32 [256][256]) -> bf16 split image [hi | lo], row-major.
// ---------------------------------------------------------------------------
__global__ __launch_bounds__(256) void convW_kernel(const float* __restrict__ w, int g)
{
    int gid = blockIdx.x * 256 + threadIdx.x;      // 8192
    int o_ = gid >> 5, kg = gid & 31, k0 = kg * 8;
    const float4* s4 = (const float4*)w + (size_t)o_ * 64 + kg * 2;
    float4 f0 = s4[0], f1 = s4[1];
    float f[8] = {f0.x, f0.y, f0.z, f0.w, f1.x, f1.y, f1.z, f1.w};
    union { unsigned short h[8]; uint4 v; } hi, lo;
#pragma unroll
    for (int j = 0; j < 8; j++) {
        __nv_bfloat16 h = __float2bfloat16_rn(f[j]);
        hi.h[j] = __bfloat16_as_ushort(h);
        lo.h[j] = __bfloat16_as_ushort(__float2bfloat16_rn(f[j] - __bfloat162float(h)));
    }
    __nv_bfloat16* dst = g_Wbf[g] + (size_t)o_ * Kimg;
    *(uint4*)(dst + k0)       = hi.v;
    *(uint4*)(dst + 256 + k0) = lo.v;
}

// ---------------------------------------------------------------------------
// bf16 GEMM via mma.sync (HMMA), 3-term split via chunk remap:
//   logical it 0-3:  A_hi x W_hi    it 4-7: A_lo x W_hi    it 8-11: A_hi x W_lo
//   A img chunk = it<8 ? it : it-8 ; W img chunk = it<8 ? (it&3) : it-4
// BM=64, BN=128, BK=64, 256 threads (2m x 4n warps), warp tile 32x32.
// 3-stage cp.async pipeline (wait_group 2); ldmatrix x4/x2; padded stride 72.
// ---------------------------------------------------------------------------
#define BM 64
#define BN 128
#define BK 64
#define SLD 72                // bf16 per smem row (144B): conflict-free ldmatrix
#define A_ST_ELT (BM * SLD)   // 4608
#define B_ST_ELT (BN * SLD)   // 9216
#define A_ST_B   (A_ST_ELT * 2)
#define B_ST_B   (B_ST_ELT * 2)
#define NSTG 3
#define GEMM_SMEM ((A_ST_ELT + B_ST_ELT) * NSTG * 2)   // 82944 bytes

__device__ __forceinline__ uint32_t smem_u32(const void* p) {
    uint32_t a;
    asm("{ .reg .u64 t; cvta.to.shared.u64 t, %1; cvt.u32.u64 %0, t; }" : "=r"(a) : "l"(p));
    return a;
}
#define CP16(dst, src) \
    asm volatile("cp.async.cg.shared.global [%0], [%1], 16;" :: "r"(dst), "l"(src))
#define CP_COMMIT() asm volatile("cp.async.commit_group;")
#define CP_WAIT2()  asm volatile("cp.async.wait_group 2;")

__global__ __launch_bounds__(256) void gemm_mma_kernel(
    const __nv_bfloat16* __restrict__ Abf, const __nv_bfloat16* __restrict__ Wbf,
    const float* __restrict__ bias, float* __restrict__ C, int coloff)
{
    extern __shared__ __align__(16) __nv_bfloat16 sm[];
    __nv_bfloat16* As0 = sm;                        // 3 stages, +A_ST_ELT each
    __nv_bfloat16* Bs0 = sm + NSTG * A_ST_ELT;      // 3 stages, +B_ST_ELT each

    const int tid = threadIdx.x;
    const int lane = tid & 31, wid = tid >> 5;
    const int wm = wid >> 2, wn = wid & 3;          // 2 x 4 warp grid
    const int m0 = blockIdx.x * BM, n0 = blockIdx.y * BN;

    // --- cp.async: A 512 16B-chunks (2/thread), B 1024 chunks (4/thread) ---
    const __nv_bfloat16* aSrc[2];
    const __nv_bfloat16* bSrc[4];
    uint32_t dA0[2], dB0[4];
#pragma unroll
    for (int i = 0; i < 2; i++) {
        int c = tid + 256 * i, row = c >> 3, col = (c & 7) * 8;
        aSrc[i] = Abf + (size_t)(m0 + row) * Kimg + col;
        dA0[i] = smem_u32(&As0[row * SLD + col]);
    }
#pragma unroll
    for (int i = 0; i < 4; i++) {
        int c = tid + 256 * i, row = c >> 3, col = (c & 7) * 8;
        bSrc[i] = Wbf + (size_t)(n0 + row) * Kimg + col;
        dB0[i] = smem_u32(&Bs0[row * SLD + col]);
    }

    // --- ldmatrix per-thread base addresses (stage 0) ---
    uint32_t aAddr0, bAddr0;
    {
        int arow = wm * 32 + (lane & 15);
        int acol = (lane >> 4) * 8;
        int l16  = lane & 15;
        int brow = wn * 32 + (l16 & 7);
        int bcol = (l16 >> 3) * 8;
        aAddr0 = smem_u32(&As0[arow * SLD + acol]);
        bAddr0 = smem_u32(&Bs0[brow * SLD + bcol]);
    }

    float d[2][4][4];
#pragma unroll
    for (int mi = 0; mi < 2; mi++)
#pragma unroll
        for (int ni = 0; ni < 4; ni++)
#pragma unroll
            for (int q = 0; q < 4; q++) d[mi][ni][q] = 0.0f;

    // preload stages 0,1,2 (it 0..2: A chunk = it, W chunk = it)
#pragma unroll
    for (int st = 0; st < NSTG; st++) {
        int k0 = st * BK;
#pragma unroll
        for (int i = 0; i < 2; i++) CP16(dA0[i] + st * A_ST_B, aSrc[i] + k0);
#pragma unroll
        for (int i = 0; i < 4; i++) CP16(dB0[i] + st * B_ST_B, bSrc[i] + k0);
        CP_COMMIT();
    }

    int st = 0;
#pragma unroll 1
    for (int it = 0; it < KIT; it++) {
        CP_WAIT2();
        __syncthreads();

        const uint32_t aA = aAddr0 + st * A_ST_B;
        const uint32_t bA = bAddr0 + st * B_ST_B;
#pragma unroll
        for (int s = 0; s < 4; s++) {               // four k16 steps
            uint32_t a[2][4], b[4][2];
#pragma unroll
            for (int mi = 0; mi < 2; mi++) {
                uint32_t addr = aA + mi * (16 * SLD * 2) + s * 32;
                asm volatile("ldmatrix.sync.aligned.m8n8.x4.shared.b16 {%0,%1,%2,%3}, [%4];"
                             : "=r"(a[mi][0]), "=r"(a[mi][1]), "=r"(a[mi][2]), "=r"(a[mi][3])
                             : "r"(addr));
            }
#pragma unroll
            for (int ni = 0; ni < 4; ni++) {
                uint32_t addr = bA + ni * (8 * SLD * 2) + s * 32;
                asm volatile("ldmatrix.sync.aligned.m8n8.x2.shared.b16 {%0,%1}, [%2];"
                             : "=r"(b[ni][0]), "=r"(b[ni][1]) : "r"(addr));
            }
#pragma unroll
            for (int mi = 0; mi < 2; mi++)
#pragma unroll
                for (int ni = 0; ni < 4; ni++)
                    asm volatile(
                        "mma.sync.aligned.m16n8k16.row.col.f32.bf16.bf16.f32 "
                        "{%0,%1,%2,%3}, {%4,%5,%6,%7}, {%8,%9}, {%0,%1,%2,%3};"
                        : "+f"(d[mi][ni][0]), "+f"(d[mi][ni][1]),
                          "+f"(d[mi][ni][2]), "+f"(d[mi][ni][3])
                        : "r"(a[mi][0]), "r"(a[mi][1]), "r"(a[mi][2]), "r"(a[mi][3]),
                          "r"(b[ni][0]), "r"(b[ni][1]));
        }
        __syncthreads();
        if (it + NSTG < KIT) {
            int j = it + NSTG;
            int kA = (j < 8 ? j : j - 8) * BK;
            int kB = (j < 8 ? (j & 3) : j - 4) * BK;
#pragma unroll
            for (int i = 0; i < 2; i++) CP16(dA0[i] + st * A_ST_B, aSrc[i] + kA);
#pragma unroll
            for (int i = 0; i < 4; i++) CP16(dB0[i] + st * B_ST_B, bSrc[i] + kB);
        }
        CP_COMMIT();   // commit even if empty to keep wait_group accounting simple
        st = (st == NSTG - 1) ? 0 : st + 1;
    }

    // epilogue: D frag -> C with bias
    const int quad = lane >> 2, tq = lane & 3;
#pragma unroll
    for (int mi = 0; mi < 2; mi++) {
        int row = m0 + wm * 32 + mi * 16 + quad;
#pragma unroll
        for (int ni = 0; ni < 4; ni++) {
            int col = n0 + wn * 32 + ni * 8 + tq * 2;
            float2 bv = *(const float2*)(bias + col);
            float2 v0 = make_float2(d[mi][ni][0] + bv.x, d[mi][ni][1] + bv.y);
            float2 v1 = make_float2(d[mi][ni][2] + bv.x, d[mi][ni][3] + bv.y);
            *(float2*)&C[(size_t)row * Cch + coloff + col] = v0;
            *(float2*)&C[(size_t)(row + 8) * Cch + coloff + col] = v1;
        }
    }
}

// ---------------------------------------------------------------------------
// Stats pass: per-row inv L2-norm + per-channel BN stats of relu(h*inv).
// Reads h, writes only g_invn (64KB) + stats. No h rewrite.
// ---------------------------------------------------------------------------
#define NR 16   // rows per warp

__global__ __launch_bounds__(256) void norm_stats_kernel(const float* __restrict__ h)
{
    __shared__ float ssum[Cch], ssq[Cch];
    const int tid = threadIdx.x, lane = tid & 31, wid = tid >> 5;
    ssum[tid] = 0.f; ssq[tid] = 0.f;
    ssum[tid + 256] = 0.f; ssq[tid + 256] = 0.f;
    __syncthreads();

    float asum[4][4], asq[4][4];
#pragma unroll
    for (int q = 0; q < 4; q++)
#pragma unroll
        for (int j = 0; j < 4; j++) { asum[q][j] = 0.f; asq[q][j] = 0.f; }

    const int row0 = blockIdx.x * (8 * NR) + wid * NR;
#pragma unroll 1
    for (int r = 0; r < NR; r++) {
        const int row = row0 + r;
        const float4* p = (const float4*)(h + (size_t)row * Cch);
        float4 v[4];
#pragma unroll
        for (int q = 0; q < 4; q++) v[q] = p[lane + 32 * q];
        float s = 0.f;
#pragma unroll
        for (int q = 0; q < 4; q++)
            s += v[q].x * v[q].x + v[q].y * v[q].y + v[q].z * v[q].z + v[q].w * v[q].w;
#pragma unroll
        for (int o = 16; o; o >>= 1) s += __shfl_xor_sync(0xffffffffu, s, o);
        float inv = 1.0f / fmaxf(sqrtf(s), 1e-12f);
        if (lane == 0) g_invn[row] = inv;
#pragma unroll
        for (int q = 0; q < 4; q++) {
            float u[4] = {v[q].x, v[q].y, v[q].z, v[q].w};
#pragma unroll
            for (int j = 0; j < 4; j++) {
                float t = fmaxf(u[j] * inv, 0.0f);
                asum[q][j] += t;
                asq[q][j]  += t * t;
            }
        }
    }
#pragma unroll
    for (int q = 0; q < 4; q++)
#pragma unroll
        for (int j = 0; j < 4; j++) {
            int c = 4 * lane + 128 * q + j;
            atomicAdd(&ssum[c], asum[q][j]);
            atomicAdd(&ssq[c],  asq[q][j]);
        }
    __syncthreads();
    for (int c = tid; c < Cch; c += 256) {
        atomicAdd(&g_stats[c],       ssum[c]);
        atomicAdd(&g_stats[Cch + c], ssq[c]);
    }
}

// ---------------------------------------------------------------------------
// Apply pass: h = relu(h*inv[row]) * scale[c] + shift[c]  (one read+write)
// ---------------------------------------------------------------------------
#define NR2 8   // rows per warp

__global__ __launch_bounds__(256) void bn_apply_kernel(
    const float* __restrict__ gamma, const float* __restrict__ beta,
    float* __restrict__ h)
{
    __shared__ float sc[Cch], sh[Cch];
    const int tid = threadIdx.x, lane = tid & 31, wid = tid >> 5;
    const float invM = 1.0f / (float)Mrows;
    for (int c = tid; c < Cch; c += 256) {
        float mu  = g_stats[c] * invM;
        float var = g_stats[Cch + c] * invM - mu * mu;
        float s   = gamma[c] * rsqrtf(var + 1e-5f);
        sc[c] = s;
        sh[c] = beta[c] - mu * s;
    }
    __syncthreads();

    const int row0 = blockIdx.x * (8 * NR2) + wid * NR2;
#pragma unroll 1
    for (int r = 0; r < NR2; r++) {
        const int row = row0 + r;
        const float inv = g_invn[row];
        float4* p = (float4*)(h + (size_t)row * Cch);
#pragma unroll
        for (int q = 0; q < 4; q++) {
            float4 v = p[lane + 32 * q];
            int c = 4 * lane + 128 * q;
            v.x = fmaxf(v.x * inv, 0.f) * sc[c + 0] + sh[c + 0];
            v.y = fmaxf(v.y * inv, 0.f) * sc[c + 1] + sh[c + 1];
            v.z = fmaxf(v.z * inv, 0.f) * sc[c + 2] + sh[c + 2];
            v.w = fmaxf(v.w * inv, 0.f) * sc[c + 3] + sh[c + 3];
            p[lane + 32 * q] = v;
        }
    }
}

// ---------------------------------------------------------------------------
// Launch
// Inputs: x, idx_neib, Wx_w, Wx_b, Wn_w, Wn_b, gamma, beta
// ---------------------------------------------------------------------------
extern "C" void kernel_launch(void* const* d_in, const int* in_sizes, int n_in,
                              void* d_out, int out_size)
{
    const float* x     = (const float*)d_in[0];
    const int*   idx   = (const int*)  d_in[1];
    const float* Wx_w  = (const float*)d_in[2];
    const float* Wx_b  = (const float*)d_in[3];
    const float* Wn_w  = (const float*)d_in[4];
    const float* Wn_b  = (const float*)d_in[5];
    const float* gamma = (const float*)d_in[6];
    const float* beta  = (const float*)d_in[7];
    float* out = (float*)d_out;

    static cudaStream_t s2 = nullptr;
    static cudaEvent_t ev_fork = nullptr, ev_join = nullptr;
    static int stream_ok = -1;
    if (stream_ok < 0) {
        bool ok = cudaFuncSetAttribute(gemm_mma_kernel,
                     cudaFuncAttributeMaxDynamicSharedMemorySize, GEMM_SMEM) == cudaSuccess;
        ok = ok && cudaStreamCreateWithFlags(&s2, cudaStreamNonBlocking) == cudaSuccess;
        ok = ok && cudaEventCreateWithFlags(&ev_fork, cudaEventDisableTiming) == cudaSuccess;
        ok = ok && cudaEventCreateWithFlags(&ev_join, cudaEventDisableTiming) == cudaSuccess;
        stream_ok = ok ? 1 : 0;
    }

    __nv_bfloat16* Wself; cudaGetSymbolAddress((void**)&Wself, g_Wbf);  // [0]
    __nv_bfloat16* Wneib = Wself + 256 * Kimg;                          // [1]
    __nv_bfloat16* Aself; cudaGetSymbolAddress((void**)&Aself, g_Aself);
    __nv_bfloat16* Aneib; cudaGetSymbolAddress((void**)&Aneib, g_Aneib);

    dim3 ggrid(Mrows / BM, 2);   // 256 x 2

    zero_stats_kernel<<<2, 512>>>();
    convW_kernel<<<32, 256>>>(Wx_w, 0);
    convW_kernel<<<32, 256>>>(Wn_w, 1);

    if (stream_ok) {
        cudaEventRecord(ev_fork, 0);
        cudaStreamWaitEvent(s2, ev_fork, 0);
        // branch B: gather (fused bf16 split) -> neighbor GEMM
        gather_mean_bf16_kernel<<<Nn, 512, 0, s2>>>(x, idx);
        gemm_mma_kernel<<<ggrid, 256, GEMM_SMEM, s2>>>(Aneib, Wneib, Wn_b, out, 256);
        cudaEventRecord(ev_join, s2);
        // branch A: convert x -> self GEMM
        convA_kernel<<<2048, 256>>>(x);
        gemm_mma_kernel<<<ggrid, 256, GEMM_SMEM>>>(Aself, Wself, Wx_b, out, 0);
        cudaStreamWaitEvent(0, ev_join, 0);
    } else {
        gather_mean_bf16_kernel<<<Nn, 512>>>(x, idx);
        convA_kernel<<<2048, 256>>>(x);
        gemm_mma_kernel<<<ggrid, 256, GEMM_SMEM>>>(Aself, Wself, Wx_b, out, 0);
        gemm_mma_kernel<<<ggrid, 256, GEMM_SMEM>>>(Aneib, Wneib, Wn_b, out, 256);
    }

    norm_stats_kernel<<<Mrows / (8 * NR), 256>>>(out);
    bn_apply_kernel<<<Mrows / (8 * NR2), 256>>>(gamma, beta, out);
}

// round 7
// speedup vs baseline: 1.7700x; 1.0220x over previous
#include <cuda_runtime.h>
#include <cuda_bf16.h>
#include <cstdint>

// Problem constants
#define Bc   8
#define Nn   2048
#define Kn   32
#define Fin  256
#define Cch  512
#define Mrows 16384
#define Kimg 512            // physical image: [hi(256) | lo(256)]
#define KIT  12             // logical K chunks of 64 (A: hi,lo,hi ; W: hi,hi,lo)

// ---------------------------------------------------------------------------
// Device-global scratch (no allocations allowed)
// ---------------------------------------------------------------------------
__device__ __align__(16) __nv_bfloat16 g_Aself[Mrows * Kimg];   // 16.8 MB
__device__ __align__(16) __nv_bfloat16 g_Aneib[Mrows * Kimg];   // 16.8 MB
__device__ __align__(16) __nv_bfloat16 g_Wbf[2][256 * Kimg];    // 2 x 262 KB
__device__ float g_stats[2 * Cch];   // zero-initialized; epilogue self-cleans
__device__ int   g_bar0;             // grid barrier counter (self-cleaned)
__device__ int   g_done;             // finalize-read counter (self-cleaned)

// ---------------------------------------------------------------------------
// bf16 hi/lo split of a float4 -> two 8B packets
// ---------------------------------------------------------------------------
__device__ __forceinline__ void split4(float4 m, uint2& hv, uint2& lv) {
    float f[4] = {m.x, m.y, m.z, m.w};
    unsigned short h[4], l[4];
#pragma unroll
    for (int j = 0; j < 4; j++) {
        __nv_bfloat16 hb = __float2bfloat16_rn(f[j]);
        h[j] = __bfloat16_as_ushort(hb);
        l[j] = __bfloat16_as_ushort(__float2bfloat16_rn(f[j] - __bfloat162float(hb)));
    }
    hv = make_uint2((uint32_t)h[0] | ((uint32_t)h[1] << 16),
                    (uint32_t)h[2] | ((uint32_t)h[3] << 16));
    lv = make_uint2((uint32_t)l[0] | ((uint32_t)l[1] << 16),
                    (uint32_t)l[2] | ((uint32_t)l[3] << 16));
}

// ---------------------------------------------------------------------------
// Gather-mean, float4-vectorized, fused bf16 split output.
// One block per n; 512 threads = 64 float4-lanes x 8 batches.
// 4-wide load batching + 4 independent accumulators for deep MLP.
// ---------------------------------------------------------------------------
__global__ __launch_bounds__(512, 2) void gather_mean_bf16_kernel(
    const float* __restrict__ x, const int* __restrict__ idx)
{
    __shared__ int sidx[Kn];
    const int n = blockIdx.x, t = threadIdx.x;
    if (t < Kn) sidx[t] = idx[n * Kn + t] * 64;   // prescaled float4 row offset
    __syncthreads();

    const int f4 = t & 63;
    const int b  = t >> 6;             // 0..7
    const float4* xb = (const float4*)x + (size_t)b * Nn * 64 + f4;

    float4 a0 = {0,0,0,0}, a1 = {0,0,0,0}, a2 = {0,0,0,0}, a3 = {0,0,0,0};
#pragma unroll
    for (int k = 0; k < Kn; k += 4) {
        float4 v0 = xb[sidx[k + 0]];
        float4 v1 = xb[sidx[k + 1]];
        float4 v2 = xb[sidx[k + 2]];
        float4 v3 = xb[sidx[k + 3]];
        a0.x += v0.x; a0.y += v0.y; a0.z += v0.z; a0.w += v0.w;
        a1.x += v1.x; a1.y += v1.y; a1.z += v1.z; a1.w += v1.w;
        a2.x += v2.x; a2.y += v2.y; a2.z += v2.z; a2.w += v2.w;
        a3.x += v3.x; a3.y += v3.y; a3.z += v3.z; a3.w += v3.w;
    }
    const float s = 1.0f / Kn;
    float4 m = make_float4(((a0.x + a1.x) + (a2.x + a3.x)) * s,
                           ((a0.y + a1.y) + (a2.y + a3.y)) * s,
                           ((a0.z + a1.z) + (a2.z + a3.z)) * s,
                           ((a0.w + a1.w) + (a2.w + a3.w)) * s);
    uint2 hv, lv;
    split4(m, hv, lv);
    __nv_bfloat16* o = g_Aneib + ((size_t)b * Nn + n) * Kimg + f4 * 4;
    *(uint2*)(o)       = hv;
    *(uint2*)(o + 256) = lv;
}

// ---------------------------------------------------------------------------
// Convert x (fp32 [Mrows][256]) -> bf16 split image [hi | lo], row-major.
// ---------------------------------------------------------------------------
__global__ __launch_bounds__(256) void convA_kernel(const float* __restrict__ src)
{
    int gid = blockIdx.x * 256 + threadIdx.x;      // Mrows*32
    int m = gid >> 5, kg = gid & 31, k0 = kg * 8;
    const float4* s4 = (const float4*)src + (size_t)m * 64 + kg * 2;
    float4 f0 = s4[0], f1 = s4[1];
    uint2 hv0, lv0, hv1, lv1;
    split4(f0, hv0, lv0);
    split4(f1, hv1, lv1);
    __nv_bfloat16* o = g_Aself + (size_t)m * Kimg;
    *(uint4*)(o + k0)       = make_uint4(hv0.x, hv0.y, hv1.x, hv1.y);
    *(uint4*)(o + 256 + k0) = make_uint4(lv0.x, lv0.y, lv1.x, lv1.y);
}

// ---------------------------------------------------------------------------
// Convert BOTH W (fp32 [256][256]) -> bf16 split images [hi | lo].
// Grid 64: blocks 0-31 -> Wx (g=0), 32-63 -> Wn (g=1).
// ---------------------------------------------------------------------------
__global__ __launch_bounds__(256) void convW_kernel(
    const float* __restrict__ wx, const float* __restrict__ wn)
{
    int g = blockIdx.x >> 5;
    const float* w = g ? wn : wx;
    int gid = (blockIdx.x & 31) * 256 + threadIdx.x;   // 8192
    int o_ = gid >> 5, kg = gid & 31, k0 = kg * 8;
    const float4* s4 = (const float4*)w + (size_t)o_ * 64 + kg * 2;
    float4 f0 = s4[0], f1 = s4[1];
    uint2 hv0, lv0, hv1, lv1;
    split4(f0, hv0, lv0);
    split4(f1, hv1, lv1);
    __nv_bfloat16* dst = g_Wbf[g] + (size_t)o_ * Kimg;
    *(uint4*)(dst + k0)       = make_uint4(hv0.x, hv0.y, hv1.x, hv1.y);
    *(uint4*)(dst + 256 + k0) = make_uint4(lv0.x, lv0.y, lv1.x, lv1.y);
}

// ---------------------------------------------------------------------------
// bf16 GEMM via mma.sync (HMMA), 3-term split via chunk remap:
//   logical it 0-3:  A_hi x W_hi    it 4-7: A_lo x W_hi    it 8-11: A_hi x W_lo
// BM=64, BN=128, BK=64, 256 threads (2m x 4n warps), warp tile 32x32.
// 3-stage cp.async pipeline; ldmatrix x4/x2; padded stride 72.
// ---------------------------------------------------------------------------
#define BM 64
#define BN 128
#define BK 64
#define SLD 72
#define A_ST_ELT (BM * SLD)
#define B_ST_ELT (BN * SLD)
#define A_ST_B   (A_ST_ELT * 2)
#define B_ST_B   (B_ST_ELT * 2)
#define NSTG 3
#define GEMM_SMEM ((A_ST_ELT + B_ST_ELT) * NSTG * 2)   // 82944 bytes

__device__ __forceinline__ uint32_t smem_u32(const void* p) {
    uint32_t a;
    asm("{ .reg .u64 t; cvta.to.shared.u64 t, %1; cvt.u32.u64 %0, t; }" : "=r"(a) : "l"(p));
    return a;
}
#define CP16(dst, src) \
    asm volatile("cp.async.cg.shared.global [%0], [%1], 16;" :: "r"(dst), "l"(src))
#define CP_COMMIT() asm volatile("cp.async.commit_group;")
#define CP_WAIT2()  asm volatile("cp.async.wait_group 2;")

__global__ __launch_bounds__(256) void gemm_mma_kernel(
    const __nv_bfloat16* __restrict__ Abf, const __nv_bfloat16* __restrict__ Wbf,
    const float* __restrict__ bias, float* __restrict__ C, int coloff)
{
    extern __shared__ __align__(16) __nv_bfloat16 sm[];
    __nv_bfloat16* As0 = sm;
    __nv_bfloat16* Bs0 = sm + NSTG * A_ST_ELT;

    const int tid = threadIdx.x;
    const int lane = tid & 31, wid = tid >> 5;
    const int wm = wid >> 2, wn = wid & 3;
    const int m0 = blockIdx.x * BM, n0 = blockIdx.y * BN;

    const __nv_bfloat16* aSrc[2];
    const __nv_bfloat16* bSrc[4];
    uint32_t dA0[2], dB0[4];
#pragma unroll
    for (int i = 0; i < 2; i++) {
        int c = tid + 256 * i, row = c >> 3, col = (c & 7) * 8;
        aSrc[i] = Abf + (size_t)(m0 + row) * Kimg + col;
        dA0[i] = smem_u32(&As0[row * SLD + col]);
    }
#pragma unroll
    for (int i = 0; i < 4; i++) {
        int c = tid + 256 * i, row = c >> 3, col = (c & 7) * 8;
        bSrc[i] = Wbf + (size_t)(n0 + row) * Kimg + col;
        dB0[i] = smem_u32(&Bs0[row * SLD + col]);
    }

    uint32_t aAddr0, bAddr0;
    {
        int arow = wm * 32 + (lane & 15);
        int acol = (lane >> 4) * 8;
        int l16  = lane & 15;
        int brow = wn * 32 + (l16 & 7);
        int bcol = (l16 >> 3) * 8;
        aAddr0 = smem_u32(&As0[arow * SLD + acol]);
        bAddr0 = smem_u32(&Bs0[brow * SLD + bcol]);
    }

    float d[2][4][4];
#pragma unroll
    for (int mi = 0; mi < 2; mi++)
#pragma unroll
        for (int ni = 0; ni < 4; ni++)
#pragma unroll
            for (int q = 0; q < 4; q++) d[mi][ni][q] = 0.0f;

#pragma unroll
    for (int st = 0; st < NSTG; st++) {
        int k0 = st * BK;
#pragma unroll
        for (int i = 0; i < 2; i++) CP16(dA0[i] + st * A_ST_B, aSrc[i] + k0);
#pragma unroll
        for (int i = 0; i < 4; i++) CP16(dB0[i] + st * B_ST_B, bSrc[i] + k0);
        CP_COMMIT();
    }

    int st = 0;
#pragma unroll 1
    for (int it = 0; it < KIT; it++) {
        CP_WAIT2();
        __syncthreads();

        const uint32_t aA = aAddr0 + st * A_ST_B;
        const uint32_t bA = bAddr0 + st * B_ST_B;
#pragma unroll
        for (int s = 0; s < 4; s++) {
            uint32_t a[2][4], b[4][2];
#pragma unroll
            for (int mi = 0; mi < 2; mi++) {
                uint32_t addr = aA + mi * (16 * SLD * 2) + s * 32;
                asm volatile("ldmatrix.sync.aligned.m8n8.x4.shared.b16 {%0,%1,%2,%3}, [%4];"
                             : "=r"(a[mi][0]), "=r"(a[mi][1]), "=r"(a[mi][2]), "=r"(a[mi][3])
                             : "r"(addr));
            }
#pragma unroll
            for (int ni = 0; ni < 4; ni++) {
                uint32_t addr = bA + ni * (8 * SLD * 2) + s * 32;
                asm volatile("ldmatrix.sync.aligned.m8n8.x2.shared.b16 {%0,%1}, [%2];"
                             : "=r"(b[ni][0]), "=r"(b[ni][1]) : "r"(addr));
            }
#pragma unroll
            for (int mi = 0; mi < 2; mi++)
#pragma unroll
                for (int ni = 0; ni < 4; ni++)
                    asm volatile(
                        "mma.sync.aligned.m16n8k16.row.col.f32.bf16.bf16.f32 "
                        "{%0,%1,%2,%3}, {%4,%5,%6,%7}, {%8,%9}, {%0,%1,%2,%3};"
                        : "+f"(d[mi][ni][0]), "+f"(d[mi][ni][1]),
                          "+f"(d[mi][ni][2]), "+f"(d[mi][ni][3])
                        : "r"(a[mi][0]), "r"(a[mi][1]), "r"(a[mi][2]), "r"(a[mi][3]),
                          "r"(b[ni][0]), "r"(b[ni][1]));
        }
        __syncthreads();
        if (it + NSTG < KIT) {
            int j = it + NSTG;
            int kA = (j < 8 ? j : j - 8) * BK;
            int kB = (j < 8 ? (j & 3) : j - 4) * BK;
#pragma unroll
            for (int i = 0; i < 2; i++) CP16(dA0[i] + st * A_ST_B, aSrc[i] + kA);
#pragma unroll
            for (int i = 0; i < 4; i++) CP16(dB0[i] + st * B_ST_B, bSrc[i] + kB);
        }
        CP_COMMIT();
        st = (st == NSTG - 1) ? 0 : st + 1;
    }

    const int quad = lane >> 2, tq = lane & 3;
#pragma unroll
    for (int mi = 0; mi < 2; mi++) {
        int row = m0 + wm * 32 + mi * 16 + quad;
#pragma unroll
        for (int ni = 0; ni < 4; ni++) {
            int col = n0 + wn * 32 + ni * 8 + tq * 2;
            float2 bv = *(const float2*)(bias + col);
            float2 v0 = make_float2(d[mi][ni][0] + bv.x, d[mi][ni][1] + bv.y);
            float2 v1 = make_float2(d[mi][ni][2] + bv.x, d[mi][ni][3] + bv.y);
            *(float2*)&C[(size_t)row * Cch + coloff + col] = v0;
            *(float2*)&C[(size_t)(row + 8) * Cch + coloff + col] = v1;
        }
    }
}

// ---------------------------------------------------------------------------
// Persistent fused epilogue: 128 co-resident blocks, 256 threads.
// Phase 1: per-row inv L2-norm (kept in smem) + channel stats (atomics to
//          pre-zeroed g_stats).
// Grid barrier (software; deterministic, graph-capturable).
// Finalize scale/shift in smem; last-to-read block self-cleans g_stats and
// the barrier counters for the next replay.
// Phase 2: h = relu(h*inv)*scale + shift on the same rows.
// ---------------------------------------------------------------------------
#define EPI_BLOCKS 128
#define EPI_ROWS   (Mrows / EPI_BLOCKS)   // 128 rows per block, 16 per warp

__global__ __launch_bounds__(256) void epilogue_kernel(
    const float* __restrict__ gamma, const float* __restrict__ beta,
    float* __restrict__ h)
{
    __shared__ float ssum[Cch], ssq[Cch];
    __shared__ float sinv[EPI_ROWS];
    __shared__ float sc[Cch], sh[Cch];
    __shared__ int slast;
    const int tid = threadIdx.x, lane = tid & 31, wid = tid >> 5;
    ssum[tid] = 0.f; ssq[tid] = 0.f;
    ssum[tid + 256] = 0.f; ssq[tid + 256] = 0.f;
    __syncthreads();

    float asum[4][4], asq[4][4];
#pragma unroll
    for (int q = 0; q < 4; q++)
#pragma unroll
        for (int j = 0; j < 4; j++) { asum[q][j] = 0.f; asq[q][j] = 0.f; }

    const int rbase = wid * 16;
    const int row0 = blockIdx.x * EPI_ROWS + rbase;
#pragma unroll 1
    for (int r = 0; r < 16; r++) {
        const float4* p = (const float4*)(h + (size_t)(row0 + r) * Cch);
        float4 v[4];
#pragma unroll
        for (int q = 0; q < 4; q++) v[q] = p[lane + 32 * q];
        float s = 0.f;
#pragma unroll
        for (int q = 0; q < 4; q++)
            s += v[q].x * v[q].x + v[q].y * v[q].y + v[q].z * v[q].z + v[q].w * v[q].w;
#pragma unroll
        for (int o = 16; o; o >>= 1) s += __shfl_xor_sync(0xffffffffu, s, o);
        float inv = 1.0f / fmaxf(sqrtf(s), 1e-12f);
        if (lane == 0) sinv[rbase + r] = inv;
#pragma unroll
        for (int q = 0; q < 4; q++) {
            float u[4] = {v[q].x, v[q].y, v[q].z, v[q].w};
#pragma unroll
            for (int j = 0; j < 4; j++) {
                float t = fmaxf(u[j] * inv, 0.0f);
                asum[q][j] += t;
                asq[q][j]  += t * t;
            }
        }
    }
#pragma unroll
    for (int q = 0; q < 4; q++)
#pragma unroll
        for (int j = 0; j < 4; j++) {
            int c = 4 * lane + 128 * q + j;
            atomicAdd(&ssum[c], asum[q][j]);
            atomicAdd(&ssq[c],  asq[q][j]);
        }
    __syncthreads();
    for (int c = tid; c < Cch; c += 256) {
        atomicAdd(&g_stats[c],       ssum[c]);
        atomicAdd(&g_stats[Cch + c], ssq[c]);
    }

    // ---- grid barrier ----
    __threadfence();
    __syncthreads();
    if (tid == 0) {
        atomicAdd(&g_bar0, 1);
        while (*(volatile int*)&g_bar0 < EPI_BLOCKS) { }
    }
    __syncthreads();
    __threadfence();

    // ---- finalize (every block; values into smem) ----
    const float invM = 1.0f / (float)Mrows;
    for (int c = tid; c < Cch; c += 256) {
        float mu  = g_stats[c] * invM;
        float var = g_stats[Cch + c] * invM - mu * mu;
        float s   = gamma[c] * rsqrtf(var + 1e-5f);
        sc[c] = s;
        sh[c] = beta[c] - mu * s;
    }
    __syncthreads();

    // ---- self-clean: last block to finish reading zeroes stats + counters ----
    if (tid == 0) slast = (atomicAdd(&g_done, 1) == EPI_BLOCKS - 1);
    __syncthreads();
    if (slast) {
        for (int c = tid; c < 2 * Cch; c += 256) g_stats[c] = 0.f;
        if (tid == 0) { g_bar0 = 0; g_done = 0; }
    }

    // ---- phase 2: apply on the same rows ----
#pragma unroll 1
    for (int r = 0; r < 16; r++) {
        const float inv = sinv[rbase + r];
        float4* p = (float4*)(h + (size_t)(row0 + r) * Cch);
#pragma unroll
        for (int q = 0; q < 4; q++) {
            float4 v = p[lane + 32 * q];
            int c = 4 * lane + 128 * q;
            v.x = fmaxf(v.x * inv, 0.f) * sc[c + 0] + sh[c + 0];
            v.y = fmaxf(v.y * inv, 0.f) * sc[c + 1] + sh[c + 1];
            v.z = fmaxf(v.z * inv, 0.f) * sc[c + 2] + sh[c + 2];
            v.w = fmaxf(v.w * inv, 0.f) * sc[c + 3] + sh[c + 3];
            p[lane + 32 * q] = v;
        }
    }
}

// ---------------------------------------------------------------------------
// Launch
// Inputs: x, idx_neib, Wx_w, Wx_b, Wn_w, Wn_b, gamma, beta
// ---------------------------------------------------------------------------
extern "C" void kernel_launch(void* const* d_in, const int* in_sizes, int n_in,
                              void* d_out, int out_size)
{
    const float* x     = (const float*)d_in[0];
    const int*   idx   = (const int*)  d_in[1];
    const float* Wx_w  = (const float*)d_in[2];
    const float* Wx_b  = (const float*)d_in[3];
    const float* Wn_w  = (const float*)d_in[4];
    const float* Wn_b  = (const float*)d_in[5];
    const float* gamma = (const float*)d_in[6];
    const float* beta  = (const float*)d_in[7];
    float* out = (float*)d_out;

    static cudaStream_t s2 = nullptr;
    static cudaEvent_t ev_fork = nullptr, ev_w = nullptr, ev_join = nullptr;
    static int stream_ok = -1;
    if (stream_ok < 0) {
        bool ok = cudaFuncSetAttribute(gemm_mma_kernel,
                     cudaFuncAttributeMaxDynamicSharedMemorySize, GEMM_SMEM) == cudaSuccess;
        ok = ok && cudaStreamCreateWithFlags(&s2, cudaStreamNonBlocking) == cudaSuccess;
        ok = ok && cudaEventCreateWithFlags(&ev_fork, cudaEventDisableTiming) == cudaSuccess;
        ok = ok && cudaEventCreateWithFlags(&ev_w, cudaEventDisableTiming) == cudaSuccess;
        ok = ok && cudaEventCreateWithFlags(&ev_join, cudaEventDisableTiming) == cudaSuccess;
        stream_ok = ok ? 1 : 0;
    }

    __nv_bfloat16* Wself; cudaGetSymbolAddress((void**)&Wself, g_Wbf);  // [0]
    __nv_bfloat16* Wneib = Wself + 256 * Kimg;                          // [1]
    __nv_bfloat16* Aself; cudaGetSymbolAddress((void**)&Aself, g_Aself);
    __nv_bfloat16* Aneib; cudaGetSymbolAddress((void**)&Aneib, g_Aneib);

    dim3 ggrid(Mrows / BM, 2);   // 256 x 2

    if (stream_ok) {
        cudaEventRecord(ev_fork, 0);
        cudaStreamWaitEvent(s2, ev_fork, 0);
        // branch B (s2): gather runs concurrent with main-stream conv/GEMM
        gather_mean_bf16_kernel<<<Nn, 512, 0, s2>>>(x, idx);
        // branch A (main): weights + x conversion, self GEMM
        convW_kernel<<<64, 256>>>(Wx_w, Wn_w);
        cudaEventRecord(ev_w, 0);
        convA_kernel<<<2048, 256>>>(x);
        gemm_mma_kernel<<<ggrid, 256, GEMM_SMEM>>>(Aself, Wself, Wx_b, out, 0);
        // branch B continues: neighbor GEMM (needs gather + convW)
        cudaStreamWaitEvent(s2, ev_w, 0);
        gemm_mma_kernel<<<ggrid, 256, GEMM_SMEM, s2>>>(Aneib, Wneib, Wn_b, out, 256);
        cudaEventRecord(ev_join, s2);
        cudaStreamWaitEvent(0, ev_join, 0);
    } else {
        gather_mean_bf16_kernel<<<Nn, 512>>>(x, idx);
        convW_kernel<<<64, 256>>>(Wx_w, Wn_w);
        convA_kernel<<<2048, 256>>>(x);
        gemm_mma_kernel<<<ggrid, 256, GEMM_SMEM>>>(Aself, Wself, Wx_b, out, 0);
        gemm_mma_kernel<<<ggrid, 256, GEMM_SMEM>>>(Aneib, Wneib, Wn_b, out, 256);
    }

    epilogue_kernel<<<EPI_BLOCKS, 256>>>(gamma, beta, out);
}

// round 10
// speedup vs baseline: 1.7736x; 1.0021x over previous
#include <cuda_runtime.h>
#include <cuda_bf16.h>
#include <cstdint>

// Problem constants
#define Bc   8
#define Nn   2048
#define Kn   32
#define Fin  256
#define Cch  512
#define Mrows 16384
#define Kimg 512            // physical image: [hi(256) | lo(256)]
#define KIT  12             // logical K chunks of 64 (A: hi,lo,hi ; W: hi,hi,lo)

// ---------------------------------------------------------------------------
// Device-global scratch (no allocations allowed)
// ---------------------------------------------------------------------------
__device__ __align__(16) __nv_bfloat16 g_Aself[Mrows * Kimg];   // 16.8 MB
__device__ __align__(16) __nv_bfloat16 g_Aneib[Mrows * Kimg];   // 16.8 MB
__device__ __align__(16) __nv_bfloat16 g_Wbf[2][256 * Kimg];    // 2 x 262 KB
__device__ float g_stats[2 * Cch];   // zero-initialized; epilogue self-cleans
__device__ int   g_bar0;             // grid barrier counter (self-cleaned)
__device__ int   g_done;             // finalize-read counter (self-cleaned)

// ---------------------------------------------------------------------------
// bf16 hi/lo split of a float4 -> two 8B packets
// ---------------------------------------------------------------------------
__device__ __forceinline__ void split4(float4 m, uint2& hv, uint2& lv) {
    float f[4] = {m.x, m.y, m.z, m.w};
    unsigned short h[4], l[4];
#pragma unroll
    for (int j = 0; j < 4; j++) {
        __nv_bfloat16 hb = __float2bfloat16_rn(f[j]);
        h[j] = __bfloat16_as_ushort(hb);
        l[j] = __bfloat16_as_ushort(__float2bfloat16_rn(f[j] - __bfloat162float(hb)));
    }
    hv = make_uint2((uint32_t)h[0] | ((uint32_t)h[1] << 16),
                    (uint32_t)h[2] | ((uint32_t)h[3] << 16));
    lv = make_uint2((uint32_t)l[0] | ((uint32_t)l[1] << 16),
                    (uint32_t)l[2] | ((uint32_t)l[3] << 16));
}

// ---------------------------------------------------------------------------
// Gather-mean, float4-vectorized, fused bf16 split output.
// ---------------------------------------------------------------------------
__global__ __launch_bounds__(512, 2) void gather_mean_bf16_kernel(
    const float* __restrict__ x, const int* __restrict__ idx)
{
    __shared__ int sidx[Kn];
    const int n = blockIdx.x, t = threadIdx.x;
    if (t < Kn) sidx[t] = idx[n * Kn + t] * 64;   // prescaled float4 row offset
    __syncthreads();

    const int f4 = t & 63;
    const int b  = t >> 6;             // 0..7
    const float4* xb = (const float4*)x + (size_t)b * Nn * 64 + f4;

    float4 a0 = {0,0,0,0}, a1 = {0,0,0,0}, a2 = {0,0,0,0}, a3 = {0,0,0,0};
#pragma unroll
    for (int k = 0; k < Kn; k += 4) {
        float4 v0 = xb[sidx[k + 0]];
        float4 v1 = xb[sidx[k + 1]];
        float4 v2 = xb[sidx[k + 2]];
        float4 v3 = xb[sidx[k + 3]];
        a0.x += v0.x; a0.y += v0.y; a0.z += v0.z; a0.w += v0.w;
        a1.x += v1.x; a1.y += v1.y; a1.z += v1.z; a1.w += v1.w;
        a2.x += v2.x; a2.y += v2.y; a2.z += v2.z; a2.w += v2.w;
        a3.x += v3.x; a3.y += v3.y; a3.z += v3.z; a3.w += v3.w;
    }
    const float s = 1.0f / Kn;
    float4 m = make_float4(((a0.x + a1.x) + (a2.x + a3.x)) * s,
                           ((a0.y + a1.y) + (a2.y + a3.y)) * s,
                           ((a0.z + a1.z) + (a2.z + a3.z)) * s,
                           ((a0.w + a1.w) + (a2.w + a3.w)) * s);
    uint2 hv, lv;
    split4(m, hv, lv);
    __nv_bfloat16* o = g_Aneib + ((size_t)b * Nn + n) * Kimg + f4 * 4;
    *(uint2*)(o)       = hv;
    *(uint2*)(o + 256) = lv;
}

// ---------------------------------------------------------------------------
// Convert x (fp32 [Mrows][256]) -> bf16 split image [hi | lo], row-major.
// ---------------------------------------------------------------------------
__global__ __launch_bounds__(256) void convA_kernel(const float* __restrict__ src)
{
    int gid = blockIdx.x * 256 + threadIdx.x;      // Mrows*32
    int m = gid >> 5, kg = gid & 31, k0 = kg * 8;
    const float4* s4 = (const float4*)src + (size_t)m * 64 + kg * 2;
    float4 f0 = s4[0], f1 = s4[1];
    uint2 hv0, lv0, hv1, lv1;
    split4(f0, hv0, lv0);
    split4(f1, hv1, lv1);
    __nv_bfloat16* o = g_Aself + (size_t)m * Kimg;
    *(uint4*)(o + k0)       = make_uint4(hv0.x, hv0.y, hv1.x, hv1.y);
    *(uint4*)(o + 256 + k0) = make_uint4(lv0.x, lv0.y, lv1.x, lv1.y);
}

// ---------------------------------------------------------------------------
// Convert BOTH W (fp32 [256][256]) -> bf16 split images [hi | lo].
// ---------------------------------------------------------------------------
__global__ __launch_bounds__(256) void convW_kernel(
    const float* __restrict__ wx, const float* __restrict__ wn)
{
    int g = blockIdx.x >> 5;
    const float* w = g ? wn : wx;
    int gid = (blockIdx.x & 31) * 256 + threadIdx.x;   // 8192
    int o_ = gid >> 5, kg = gid & 31, k0 = kg * 8;
    const float4* s4 = (const float4*)w + (size_t)o_ * 64 + kg * 2;
    float4 f0 = s4[0], f1 = s4[1];
    uint2 hv0, lv0, hv1, lv1;
    split4(f0, hv0, lv0);
    split4(f1, hv1, lv1);
    __nv_bfloat16* dst = g_Wbf[g] + (size_t)o_ * Kimg;
    *(uint4*)(dst + k0)       = make_uint4(hv0.x, hv0.y, hv1.x, hv1.y);
    *(uint4*)(dst + 256 + k0) = make_uint4(lv0.x, lv0.y, lv1.x, lv1.y);
}

// ---------------------------------------------------------------------------
// bf16 GEMM via mma.sync (HMMA), 3-term split via chunk remap:
//   logical it 0-3:  A_hi x W_hi    it 4-7: A_lo x W_hi    it 8-11: A_hi x W_lo
// BM=128, BN=128, BK=64, 256 threads (2m x 4n warps), warp tile 64x32:
//   per k16: 4 ldmatrix.x4 (A) + 2 ldmatrix.x4 (B) -> 16 HMMA  (ratio 6:16)
// 3-stage cp.async pipeline; padded smem stride 72 bf16.
// ---------------------------------------------------------------------------
#define BM 128
#define BN 128
#define BK 64
#define SLD 72
#define A_ST_ELT (BM * SLD)             // 9216
#define B_ST_ELT (BN * SLD)             // 9216
#define A_ST_B   (A_ST_ELT * 2)
#define B_ST_B   (B_ST_ELT * 2)
#define NSTG 3
#define GEMM_SMEM ((A_ST_ELT + B_ST_ELT) * NSTG * 2)   // 110592 bytes

__device__ __forceinline__ uint32_t smem_u32(const void* p) {
    uint32_t a;
    asm("{ .reg .u64 t; cvta.to.shared.u64 t, %1; cvt.u32.u64 %0, t; }" : "=r"(a) : "l"(p));
    return a;
}
#define CP16(dst, src) \
    asm volatile("cp.async.cg.shared.global [%0], [%1], 16;" :: "r"(dst), "l"(src))
#define CP_COMMIT() asm volatile("cp.async.commit_group;")
#define CP_WAIT2()  asm volatile("cp.async.wait_group 2;")

__global__ __launch_bounds__(256, 2) void gemm_mma_kernel(
    const __nv_bfloat16* __restrict__ Abf, const __nv_bfloat16* __restrict__ Wbf,
    const float* __restrict__ bias, float* __restrict__ C, int coloff)
{
    extern __shared__ __align__(16) __nv_bfloat16 sm[];
    __nv_bfloat16* As0 = sm;
    __nv_bfloat16* Bs0 = sm + NSTG * A_ST_ELT;

    const int tid = threadIdx.x;
    const int lane = tid & 31, wid = tid >> 5;
    const int wm = wid >> 2, wn = wid & 3;          // 2 x 4 warp grid
    const int m0 = blockIdx.x * BM, n0 = blockIdx.y * BN;

    // --- cp.async: A and B each 1024 16B-chunks -> 4/thread, stride 32 rows ---
    const int lrow = tid >> 3, lcol = (tid & 7) * 8;
    const __nv_bfloat16* aSrc = Abf + (size_t)(m0 + lrow) * Kimg + lcol;
    const __nv_bfloat16* bSrc = Wbf + (size_t)(n0 + lrow) * Kimg + lcol;
    const uint32_t dA0 = smem_u32(&As0[lrow * SLD + lcol]);
    const uint32_t dB0 = smem_u32(&Bs0[lrow * SLD + lcol]);
    const int srcStep = 32 * Kimg;                  // elements per i-step
    const int dstStep = 32 * SLD * 2;               // bytes per i-step

    // --- ldmatrix per-thread base addresses (stage 0) ---
    const int l16 = lane & 15, lhi = (lane >> 4) * 8;
    const uint32_t aAddr0 = smem_u32(&As0[(wm * 64 + l16) * SLD + lhi]);
    const uint32_t bAddr0 = smem_u32(&Bs0[(wn * 32 + l16) * SLD + lhi]);

    float d[4][4][4];
#pragma unroll
    for (int mi = 0; mi < 4; mi++)
#pragma unroll
        for (int ni = 0; ni < 4; ni++)
#pragma unroll
            for (int q = 0; q < 4; q++) d[mi][ni][q] = 0.0f;

    // preload stages 0,1,2 (it 0..2: A chunk = it, W chunk = it)
#pragma unroll
    for (int st = 0; st < NSTG; st++) {
        int k0 = st * BK;
#pragma unroll
        for (int i = 0; i < 4; i++) {
            CP16(dA0 + st * A_ST_B + i * dstStep, aSrc + i * srcStep + k0);
            CP16(dB0 + st * B_ST_B + i * dstStep, bSrc + i * srcStep + k0);
        }
        CP_COMMIT();
    }

    int st = 0;
#pragma unroll 1
    for (int it = 0; it < KIT; it++) {
        CP_WAIT2();
        __syncthreads();

        const uint32_t aA = aAddr0 + st * A_ST_B;
        const uint32_t bA = bAddr0 + st * B_ST_B;
#pragma unroll
        for (int s = 0; s < 4; s++) {               // four k16 steps
            uint32_t a[4][4], b[4][2];
#pragma unroll
            for (int mi = 0; mi < 4; mi++) {
                uint32_t addr = aA + mi * (16 * SLD * 2) + s * 32;
                asm volatile("ldmatrix.sync.aligned.m8n8.x4.shared.b16 {%0,%1,%2,%3}, [%4];"
                             : "=r"(a[mi][0]), "=r"(a[mi][1]), "=r"(a[mi][2]), "=r"(a[mi][3])
                             : "r"(addr));
            }
#pragma unroll
            for (int ng = 0; ng < 2; ng++) {        // 16 n-cols per x4
                uint32_t r0, r1, r2, r3;
                uint32_t addr = bA + ng * (16 * SLD * 2) + s * 32;
                asm volatile("ldmatrix.sync.aligned.m8n8.x4.shared.b16 {%0,%1,%2,%3}, [%4];"
                             : "=r"(r0), "=r"(r1), "=r"(r2), "=r"(r3) : "r"(addr));
                b[2 * ng + 0][0] = r0; b[2 * ng + 0][1] = r2;
                b[2 * ng + 1][0] = r1; b[2 * ng + 1][1] = r3;
            }
#pragma unroll
            for (int mi = 0; mi < 4; mi++)
#pragma unroll
                for (int ni = 0; ni < 4; ni++)
                    asm volatile(
                        "mma.sync.aligned.m16n8k16.row.col.f32.bf16.bf16.f32 "
                        "{%0,%1,%2,%3}, {%4,%5,%6,%7}, {%8,%9}, {%0,%1,%2,%3};"
                        : "+f"(d[mi][ni][0]), "+f"(d[mi][ni][1]),
                          "+f"(d[mi][ni][2]), "+f"(d[mi][ni][3])
                        : "r"(a[mi][0]), "r"(a[mi][1]), "r"(a[mi][2]), "r"(a[mi][3]),
                          "r"(b[ni][0]), "r"(b[ni][1]));
        }
        __syncthreads();
        if (it + NSTG < KIT) {
            int j = it + NSTG;
            int kA = (j < 8 ? j : j - 8) * BK;
            int kB = (j < 8 ? (j & 3) : j - 4) * BK;
#pragma unroll
            for (int i = 0; i < 4; i++) {
                CP16(dA0 + st * A_ST_B + i * dstStep, aSrc + i * srcStep + kA);
                CP16(dB0 + st * B_ST_B + i * dstStep, bSrc + i * srcStep + kB);
            }
        }
        CP_COMMIT();
        st = (st == NSTG - 1) ? 0 : st + 1;
    }

    // epilogue: D frag -> C with bias
    const int quad = lane >> 2, tq = lane & 3;
#pragma unroll
    for (int mi = 0; mi < 4; mi++) {
        int row = m0 + wm * 64 + mi * 16 + quad;
#pragma unroll
        for (int ni = 0; ni < 4; ni++) {
            int col = n0 + wn * 32 + ni * 8 + tq * 2;
            float2 bv = *(const float2*)(bias + col);
            float2 v0 = make_float2(d[mi][ni][0] + bv.x, d[mi][ni][1] + bv.y);
            float2 v1 = make_float2(d[mi][ni][2] + bv.x, d[mi][ni][3] + bv.y);
            *(float2*)&C[(size_t)row * Cch + coloff + col] = v0;
            *(float2*)&C[(size_t)(row + 8) * Cch + coloff + col] = v1;
        }
    }
}

// ---------------------------------------------------------------------------
// Persistent fused epilogue (unchanged from R7).
// ---------------------------------------------------------------------------
#define EPI_BLOCKS 128
#define EPI_ROWS   (Mrows / EPI_BLOCKS)   // 128 rows per block, 16 per warp

__global__ __launch_bounds__(256) void epilogue_kernel(
    const float* __restrict__ gamma, const float* __restrict__ beta,
    float* __restrict__ h)
{
    __shared__ float ssum[Cch], ssq[Cch];
    __shared__ float sinv[EPI_ROWS];
    __shared__ float sc[Cch], sh[Cch];
    __shared__ int slast;
    const int tid = threadIdx.x, lane = tid & 31, wid = tid >> 5;
    ssum[tid] = 0.f; ssq[tid] = 0.f;
    ssum[tid + 256] = 0.f; ssq[tid + 256] = 0.f;
    __syncthreads();

    float asum[4][4], asq[4][4];
#pragma unroll
    for (int q = 0; q < 4; q++)
#pragma unroll
        for (int j = 0; j < 4; j++) { asum[q][j] = 0.f; asq[q][j] = 0.f; }

    const int rbase = wid * 16;
    const int row0 = blockIdx.x * EPI_ROWS + rbase;
#pragma unroll 1
    for (int r = 0; r < 16; r++) {
        const float4* p = (const float4*)(h + (size_t)(row0 + r) * Cch);
        float4 v[4];
#pragma unroll
        for (int q = 0; q < 4; q++) v[q] = p[lane + 32 * q];
        float s = 0.f;
#pragma unroll
        for (int q = 0; q < 4; q++)
            s += v[q].x * v[q].x + v[q].y * v[q].y + v[q].z * v[q].z + v[q].w * v[q].w;
#pragma unroll
        for (int o = 16; o; o >>= 1) s += __shfl_xor_sync(0xffffffffu, s, o);
        float inv = 1.0f / fmaxf(sqrtf(s), 1e-12f);
        if (lane == 0) sinv[rbase + r] = inv;
#pragma unroll
        for (int q = 0; q < 4; q++) {
            float u[4] = {v[q].x, v[q].y, v[q].z, v[q].w};
#pragma unroll
            for (int j = 0; j < 4; j++) {
                float t = fmaxf(u[j] * inv, 0.0f);
                asum[q][j] += t;
                asq[q][j]  += t * t;
            }
        }
    }
#pragma unroll
    for (int q = 0; q < 4; q++)
#pragma unroll
        for (int j = 0; j < 4; j++) {
            int c = 4 * lane + 128 * q + j;
            atomicAdd(&ssum[c], asum[q][j]);
            atomicAdd(&ssq[c],  asq[q][j]);
        }
    __syncthreads();
    for (int c = tid; c < Cch; c += 256) {
        atomicAdd(&g_stats[c],       ssum[c]);
        atomicAdd(&g_stats[Cch + c], ssq[c]);
    }

    // ---- grid barrier ----
    __threadfence();
    __syncthreads();
    if (tid == 0) {
        atomicAdd(&g_bar0, 1);
        while (*(volatile int*)&g_bar0 < EPI_BLOCKS) { }
    }
    __syncthreads();
    __threadfence();

    // ---- finalize (every block; values into smem) ----
    const float invM = 1.0f / (float)Mrows;
    for (int c = tid; c < Cch; c += 256) {
        float mu  = g_stats[c] * invM;
        float var = g_stats[Cch + c] * invM - mu * mu;
        float s   = gamma[c] * rsqrtf(var + 1e-5f);
        sc[c] = s;
        sh[c] = beta[c] - mu * s;
    }
    __syncthreads();

    // ---- self-clean: last block to finish reading zeroes stats + counters ----
    if (tid == 0) slast = (atomicAdd(&g_done, 1) == EPI_BLOCKS - 1);
    __syncthreads();
    if (slast) {
        for (int c = tid; c < 2 * Cch; c += 256) g_stats[c] = 0.f;
        if (tid == 0) { g_bar0 = 0; g_done = 0; }
    }

    // ---- phase 2: apply on the same rows ----
#pragma unroll 1
    for (int r = 0; r < 16; r++) {
        const float inv = sinv[rbase + r];
        float4* p = (float4*)(h + (size_t)(row0 + r) * Cch);
#pragma unroll
        for (int q = 0; q < 4; q++) {
            float4 v = p[lane + 32 * q];
            int c = 4 * lane + 128 * q;
            v.x = fmaxf(v.x * inv, 0.f) * sc[c + 0] + sh[c + 0];
            v.y = fmaxf(v.y * inv, 0.f) * sc[c + 1] + sh[c + 1];
            v.z = fmaxf(v.z * inv, 0.f) * sc[c + 2] + sh[c + 2];
            v.w = fmaxf(v.w * inv, 0.f) * sc[c + 3] + sh[c + 3];
            p[lane + 32 * q] = v;
        }
    }
}

// ---------------------------------------------------------------------------
// Launch
// Inputs: x, idx_neib, Wx_w, Wx_b, Wn_w, Wn_b, gamma, beta
// ---------------------------------------------------------------------------
extern "C" void kernel_launch(void* const* d_in, const int* in_sizes, int n_in,
                              void* d_out, int out_size)
{
    const float* x     = (const float*)d_in[0];
    const int*   idx   = (const int*)  d_in[1];
    const float* Wx_w  = (const float*)d_in[2];
    const float* Wx_b  = (const float*)d_in[3];
    const float* Wn_w  = (const float*)d_in[4];
    const float* Wn_b  = (const float*)d_in[5];
    const float* gamma = (const float*)d_in[6];
    const float* beta  = (const float*)d_in[7];
    float* out = (float*)d_out;

    static cudaStream_t s2 = nullptr;
    static cudaEvent_t ev_fork = nullptr, ev_w = nullptr, ev_join = nullptr;
    static int stream_ok = -1;
    if (stream_ok < 0) {
        bool ok = cudaFuncSetAttribute(gemm_mma_kernel,
                     cudaFuncAttributeMaxDynamicSharedMemorySize, GEMM_SMEM) == cudaSuccess;
        ok = ok && cudaStreamCreateWithFlags(&s2, cudaStreamNonBlocking) == cudaSuccess;
        ok = ok && cudaEventCreateWithFlags(&ev_fork, cudaEventDisableTiming) == cudaSuccess;
        ok = ok && cudaEventCreateWithFlags(&ev_w, cudaEventDisableTiming) == cudaSuccess;
        ok = ok && cudaEventCreateWithFlags(&ev_join, cudaEventDisableTiming) == cudaSuccess;
        stream_ok = ok ? 1 : 0;
    }

    __nv_bfloat16* Wself; cudaGetSymbolAddress((void**)&Wself, g_Wbf);  // [0]
    __nv_bfloat16* Wneib = Wself + 256 * Kimg;                          // [1]
    __nv_bfloat16* Aself; cudaGetSymbolAddress((void**)&Aself, g_Aself);
    __nv_bfloat16* Aneib; cudaGetSymbolAddress((void**)&Aneib, g_Aneib);

    dim3 ggrid(Mrows / BM, 2);   // 128 x 2

    if (stream_ok) {
        cudaEventRecord(ev_fork, 0);
        cudaStreamWaitEvent(s2, ev_fork, 0);
        // branch B (s2): gather runs concurrent with main-stream conv/GEMM
        gather_mean_bf16_kernel<<<Nn, 512, 0, s2>>>(x, idx);
        // branch A (main): weights + x conversion, self GEMM
        convW_kernel<<<64, 256>>>(Wx_w, Wn_w);
        cudaEventRecord(ev_w, 0);
        convA_kernel<<<2048, 256>>>(x);
        gemm_mma_kernel<<<ggrid, 256, GEMM_SMEM>>>(Aself, Wself, Wx_b, out, 0);
        // branch B continues: neighbor GEMM (needs gather + convW)
        cudaStreamWaitEvent(s2, ev_w, 0);
        gemm_mma_kernel<<<ggrid, 256, GEMM_SMEM, s2>>>(Aneib, Wneib, Wn_b, out, 256);
        cudaEventRecord(ev_join, s2);
        cudaStreamWaitEvent(0, ev_join, 0);
    } else {
        gather_mean_bf16_kernel<<<Nn, 512>>>(x, idx);
        convW_kernel<<<64, 256>>>(Wx_w, Wn_w);
        convA_kernel<<<2048, 256>>>(x);
        gemm_mma_kernel<<<ggrid, 256, GEMM_SMEM>>>(Aself, Wself, Wx_b, out, 0);
        gemm_mma_kernel<<<ggrid, 256, GEMM_SMEM, 0>>>(Aneib, Wneib, Wn_b, out, 256);
    }

    epilogue_kernel<<<EPI_BLOCKS, 256>>>(gamma, beta, out);
}